// round 13
// baseline (speedup 1.0000x reference)
#include <cuda_runtime.h>
#include <cuda_fp16.h>
#include <cstdint>

// ---------------------------------------------------------------------------
// VSN on GB300 — Round 13: conv_mega (all conversions, one launch) +
// tail_kernel (G2 GEMM + wlogits + enc_combine fused); R12 mega unchanged.
// B=8,T=2048,NV=16,D=256 -> BT=16384, DIN=4096
// ---------------------------------------------------------------------------

#define BT_TOK 16384L
#define DDIM   256
#define DIN    4096

// ---------------- scratch (bytes) ----------------
#define O_VH    0ULL            // vars fp16 [16384,4096]          128MB
#define O_H1    134217728ULL    // h1 fp16 [16384,256]
#define O_H2F   142606336ULL    // (unused)
#define O_E     159383552ULL    // E=glu+x fp16 16x[16384,256]     128MB
#define O_SKIP  293601280ULL    // skip fp32 [16384,16]
#define O_G1    294649856ULL    // Wg1^T fp16 [256,4096]
#define O_G2    296747008ULL    // Wg2^T fp16 [256,256]
#define O_W1    296878080ULL    // Wv1^T fp16 16x[256,256]
#define O_W2    298975232ULL
#define O_W3    301072384ULL    // Wv3^T perm fp16 16x[512,256]
#define G_TOTAL 305266688ULL

__device__ __align__(1024) unsigned char g_buf[G_TOTAL];

// ---------------- helpers ----------------
__device__ __forceinline__ uint32_t smem_u32(const void* p) {
    uint32_t a;
    asm("{ .reg .u64 t; cvta.to.shared.u64 t, %1; cvt.u32.u64 %0, t; }" : "=r"(a) : "l"(p));
    return a;
}
__device__ __forceinline__ void cpasync16(uint32_t dst, const void* src) {
    asm volatile("cp.async.cg.shared.global [%0], [%1], 16;" :: "r"(dst), "l"(src));
}
#define CP_COMMIT() asm volatile("cp.async.commit_group;" ::: "memory")
#define CP_WAIT(n)  asm volatile("cp.async.wait_group %0;" :: "n"(n) : "memory")

__device__ __forceinline__ void ldsm_x4(uint32_t (&r)[4], uint32_t addr) {
    asm volatile("ldmatrix.sync.aligned.m8n8.x4.shared.b16 {%0,%1,%2,%3}, [%4];"
        : "=r"(r[0]), "=r"(r[1]), "=r"(r[2]), "=r"(r[3]) : "r"(addr));
}
__device__ __forceinline__ void mma16816(float (&c)[4], const uint32_t (&a)[4],
                                         uint32_t b0, uint32_t b1) {
    asm volatile("mma.sync.aligned.m16n8k16.row.col.f32.f16.f16.f32 "
        "{%0,%1,%2,%3}, {%4,%5,%6,%7}, {%8,%9}, {%0,%1,%2,%3};"
        : "+f"(c[0]), "+f"(c[1]), "+f"(c[2]), "+f"(c[3])
        : "r"(a[0]), "r"(a[1]), "r"(a[2]), "r"(a[3]), "r"(b0), "r"(b1));
}
__device__ __forceinline__ uint32_t hadd2_f32(uint32_t e, uint32_t x) {
    __half2 he = *reinterpret_cast<__half2*>(&e);
    __half2 hx = *reinterpret_cast<__half2*>(&x);
    float2 fe = __half22float2(he);
    float2 fx = __half22float2(hx);
    __half2 r = __floats2half2_rn(fe.x + fx.x, fe.y + fx.y);
    return *reinterpret_cast<uint32_t*>(&r);
}

// ---------------------------------------------------------------------------
// conv_mega: all conversions in one launch.
// [0,64) G2T, [64,1088) G1T, [1088,2112) W1T, [2112,3136) W2T,
// [3136,5184) W3T(perm), [5184,37952) conv_split
// ---------------------------------------------------------------------------
__device__ __noinline__ void dev_wT(const float* W, __half* TH, int K, int N,
                                    int bx, int by, int bz, float (*tile)[33])
{
    const size_t vb = (size_t)bz * K * N;
    const int k0 = by * 32, n0 = bx * 32;
    const int tx = threadIdx.x & 31, ty = threadIdx.x >> 5;
#pragma unroll
    for (int i = 0; i < 4; i++)
        tile[ty + i * 8][tx] = W[vb + (size_t)(k0 + ty + i * 8) * N + n0 + tx];
    __syncthreads();
#pragma unroll
    for (int i = 0; i < 4; i++) {
        int n = ty + i * 8;
        TH[vb + (size_t)(n0 + n) * K + k0 + tx] = __float2half_rn(tile[tx][n]);
    }
}

__device__ __noinline__ void dev_wT3(const float* W, __half* TH,
                                     int bx, int by, int bz, float (*tile)[33])
{
    const size_t vbs = (size_t)bz * 256 * 512;
    const size_t vbd = (size_t)bz * 512 * 256;
    const int k0 = by * 32, c0 = bx * 32;
    const int tx = threadIdx.x & 31, ty = threadIdx.x >> 5;
#pragma unroll
    for (int i = 0; i < 4; i++)
        tile[ty + i * 8][tx] = W[vbs + (size_t)(k0 + ty + i * 8) * 512 + c0 + tx];
    __syncthreads();
#pragma unroll
    for (int i = 0; i < 4; i++) {
        int c = c0 + ty + i * 8;
        int orow = (c < 256) ? (2 * c) : (2 * (c - 256) + 1);
        TH[vbd + (size_t)orow * 256 + k0 + tx] = __float2half_rn(tile[tx][ty + i * 8]);
    }
}

__device__ __noinline__ void dev_split(const float* x, __half* h, int bidx)
{
    size_t i = ((size_t)bidx * 512 + threadIdx.x * 2) * 4;
#pragma unroll
    for (int u = 0; u < 2; u++) {
        float4 v = *reinterpret_cast<const float4*>(x + i + u * 4);
        *reinterpret_cast<__half2*>(h + i + u * 4)     = __floats2half2_rn(v.x, v.y);
        *reinterpret_cast<__half2*>(h + i + u * 4 + 2) = __floats2half2_rn(v.z, v.w);
    }
}

__global__ __launch_bounds__(256)
void conv_mega(const float* __restrict__ vars, __half* __restrict__ VH,
               const float* __restrict__ Wg1, __half* __restrict__ G1T,
               const float* __restrict__ Wg2, __half* __restrict__ G2T,
               const float* __restrict__ Wv1, __half* __restrict__ W1T,
               const float* __restrict__ Wv2, __half* __restrict__ W2T,
               const float* __restrict__ Wv3, __half* __restrict__ W3T)
{
    __shared__ float tile[32][33];
    const int b = blockIdx.x;
    if (b < 64) {
        dev_wT(Wg2, G2T, 256, 256, b & 7, b >> 3, 0, tile);
    } else if (b < 1088) {
        int i = b - 64;  dev_wT(Wg1, G1T, 4096, 256, i & 7, i >> 3, 0, tile);
    } else if (b < 2112) {
        int i = b - 1088; dev_wT(Wv1, W1T, 256, 256, i & 7, (i >> 3) & 7, i >> 6, tile);
    } else if (b < 3136) {
        int i = b - 2112; dev_wT(Wv2, W2T, 256, 256, i & 7, (i >> 3) & 7, i >> 6, tile);
    } else if (b < 5184) {
        int i = b - 3136; dev_wT3(Wv3, W3T, i & 15, (i >> 4) & 7, i >> 7, tile);
    } else {
        dev_split(vars, VH, b - 5184);
    }
}

// ---------------------------------------------------------------------------
#define RS 72
#define OFF_B  18432
#define ST_SIZE 36864
#define SMEM_TOT 110592

#define ACH 9216u
#define FA0 0u
#define FA1 36864u
#define FWB 73728u

// ---- G1 GEMM body (ELU + fp16 out). K=4096, bidx in [0,256) ----
__device__ __noinline__ void dev_g1(unsigned char* sm, uint32_t sb,
                                    const __half* VH, const __half* G1T,
                                    const float* bg1, __half* H1, int bidx)
{
    const int tid = threadIdx.x;
    const int lane = tid & 31, wid = tid >> 5;
    const int wm = wid & 1, wn = wid >> 1;
    const int nb = (bidx & 1) * 128;
    const int m0 = (bidx >> 1) * 128;

    const __half* Ap  = VH + (size_t)m0 * DIN;
    const __half* Bhp = G1T + (size_t)nb * DIN;
    const int lr = tid >> 3;
    const int lc = (tid & 7) * 8;

    float acc[4][4][4];
#pragma unroll
    for (int i = 0; i < 4; i++)
#pragma unroll
        for (int j = 0; j < 4; j++)
#pragma unroll
            for (int k = 0; k < 4; k++) acc[i][j][k] = 0.f;

    auto load_stage = [&](int s, int k0) {
        const uint32_t base = sb + s * ST_SIZE;
#pragma unroll
        for (int t = 0; t < 4; t++) {
            const int row = lr + t * 32;
            const uint32_t doff = (uint32_t)(row * RS + lc) * 2;
            cpasync16(base + doff,         Ap  + (size_t)row * DIN + k0 + lc);
            cpasync16(base + OFF_B + doff, Bhp + (size_t)row * DIN + k0 + lc);
        }
    };

    const uint32_t aoff = (uint32_t)(((wm * 64 + (lane & 15)) * RS + (lane >> 4) * 8) * 2);
    const uint32_t boff = (uint32_t)(((wn * 32 + (lane & 15)) * RS + (lane >> 4) * 8) * 2);

    load_stage(0, 0);  CP_COMMIT();
    load_stage(1, 64); CP_COMMIT();

    int sidx = 0;
    for (int c = 0; c < 64; c++) {
        CP_WAIT(1);
        __syncthreads();
        const uint32_t base = sb + sidx * ST_SIZE;
#pragma unroll
        for (int kc = 0; kc < 64; kc += 16) {
            uint32_t a[4][4], bh[2][4];
#pragma unroll
            for (int mt = 0; mt < 4; mt++)
                ldsm_x4(a[mt], base + aoff + mt * (16 * RS * 2) + kc * 2);
#pragma unroll
            for (int p = 0; p < 2; p++)
                ldsm_x4(bh[p], base + OFF_B + boff + p * (16 * RS * 2) + kc * 2);
#pragma unroll
            for (int mt = 0; mt < 4; mt++)
#pragma unroll
                for (int q = 0; q < 4; q++)
                    mma16816(acc[mt][q], a[mt], bh[q >> 1][q & 1], bh[q >> 1][(q & 1) + 2]);
        }
        __syncthreads();
        if (c + 2 < 64) {
            int ns = sidx + 2; if (ns >= 3) ns -= 3;
            load_stage(ns, (c + 2) * 64);
        }
        CP_COMMIT();
        if (++sidx == 3) sidx = 0;
    }

    const int gid = lane >> 2, tig = lane & 3;
#pragma unroll
    for (int mt = 0; mt < 4; mt++) {
#pragma unroll
        for (int q = 0; q < 4; q++) {
            const int m = m0 + wm * 64 + mt * 16 + gid;
            const int n = nb + wn * 32 + q * 8 + tig * 2;
            const float b0 = bg1[n], b1 = bg1[n + 1];
            float x0 = acc[mt][q][0] + b0, x1 = acc[mt][q][1] + b1;
            float y0 = acc[mt][q][2] + b0, y1 = acc[mt][q][3] + b1;
            x0 = (x0 > 0.f) ? x0 : expm1f(x0);
            x1 = (x1 > 0.f) ? x1 : expm1f(x1);
            y0 = (y0 > 0.f) ? y0 : expm1f(y0);
            y1 = (y1 > 0.f) ? y1 : expm1f(y1);
            __half* d0 = H1 + (size_t)m * 256 + n;
            *reinterpret_cast<__half2*>(d0) = __floats2half2_rn(x0, x1);
            *reinterpret_cast<__half2*>(d0 + 8 * 256) = __floats2half2_rn(y0, y1);
        }
    }
}

// ---- skip body: bidx in [0,1024) ----
__device__ __noinline__ void dev_skip(unsigned char* sm,
                                      const __half* vh, const float* Wgs,
                                      const float* bgs, float* skipOut, int bidx)
{
    __half (*As)[256] = reinterpret_cast<__half (*)[256]>(sm);
    float (*Ws)[16]  = reinterpret_cast<float (*)[16]>(sm + 8192);
    const int tid = threadIdx.x;
    const long t0 = (long)bidx * 16;
    const int o = tid & 15;
    const int tr = tid >> 4;
    float s = 0.f;
    for (int k0 = 0; k0 < DIN; k0 += 256) {
        {
            const int r = tid >> 4;
            const int cc = (tid & 15) * 16;
            *reinterpret_cast<uint4*>(&As[r][cc]) =
                *reinterpret_cast<const uint4*>(vh + (t0 + r) * DIN + k0 + cc);
            *reinterpret_cast<uint4*>(&As[r][cc + 8]) =
                *reinterpret_cast<const uint4*>(vh + (t0 + r) * DIN + k0 + cc + 8);
        }
        {
            const int r = tid;
            *reinterpret_cast<float4*>(&Ws[r][0])  = *reinterpret_cast<const float4*>(Wgs + (long)(k0 + r) * 16 + 0);
            *reinterpret_cast<float4*>(&Ws[r][4])  = *reinterpret_cast<const float4*>(Wgs + (long)(k0 + r) * 16 + 4);
            *reinterpret_cast<float4*>(&Ws[r][8])  = *reinterpret_cast<const float4*>(Wgs + (long)(k0 + r) * 16 + 8);
            *reinterpret_cast<float4*>(&Ws[r][12]) = *reinterpret_cast<const float4*>(Wgs + (long)(k0 + r) * 16 + 12);
        }
        __syncthreads();
#pragma unroll 16
        for (int kk = 0; kk < 256; kk++) s += __half2float(As[tr][kk]) * Ws[kk][o];
        __syncthreads();
    }
    skipOut[(t0 + tr) * 16 + o] = s + bgs[o];
}

// ---- fused per-variable chain body: bidx in [0,4096) ----
__device__ __noinline__ void dev_fused(unsigned char* sm, uint32_t sb,
                                       const __half* VH,
                                       const __half* W1T, const __half* W2T,
                                       const __half* W3T,
                                       const float* bv1, const float* bv2,
                                       const float* bv3, __half* E, int bidx)
{
    const int tid = threadIdx.x;
    const int lane = tid & 31, wid = tid >> 5;
    const int wm = wid & 1, wn = wid >> 1;
    const int gid = lane >> 2, tig = lane & 3;
    const int v = bidx >> 8;
    const int m0 = (bidx & 255) * 64;

    {
        const __half* xp = VH + (size_t)m0 * DIN + v * 256;
#pragma unroll
        for (int t = 0; t < 8; t++) {
            const int id = tid + t * 256;
            const int ch = id >> 9;
            const int rem = id & 511;
            const int row = rem >> 3;
            const int lc8 = (rem & 7) * 8;
            cpasync16(sb + FA0 + ch * ACH + (uint32_t)(row * RS + lc8) * 2,
                      xp + (size_t)row * DIN + ch * 64 + lc8);
        }
        CP_COMMIT();
    }

    const uint32_t aoff = (uint32_t)(((wm * 32 + (lane & 15)) * RS + (lane >> 4) * 8) * 2);
    const uint32_t boff = (uint32_t)(((wn * 32 + (lane & 15)) * RS + (lane >> 4) * 8) * 2);
    const int lr = tid >> 3;
    const int lc = (tid & 7) * 8;

    for (int stage = 0; stage < 3; stage++) {
        const __half* W = (stage == 0) ? (W1T + (size_t)v * 65536)
                        : (stage == 1) ? (W2T + (size_t)v * 65536)
                                       : (W3T + (size_t)v * 131072);
        const int nPass = (stage == 2) ? 4 : 2;
        const uint32_t aBuf = (stage == 1) ? FA1 : FA0;
        const uint32_t oBuf = (stage == 0) ? FA1 : FA0;

        for (int np = 0; np < nPass; np++) {
            float acc[2][4][4];
#pragma unroll
            for (int i = 0; i < 2; i++)
#pragma unroll
                for (int j = 0; j < 4; j++)
#pragma unroll
                    for (int k = 0; k < 4; k++) acc[i][j][k] = 0.f;

            const __half* Wp = W + (size_t)(np * 128) * 256;
#pragma unroll
            for (int pc = 0; pc < 2; pc++) {
#pragma unroll
                for (int t = 0; t < 4; t++) {
                    const int row = lr + t * 32;
                    cpasync16(sb + FWB + pc * 18432 + (uint32_t)(row * RS + lc) * 2,
                              Wp + (size_t)row * 256 + pc * 64 + lc);
                }
                CP_COMMIT();
            }

            for (int c = 0; c < 4; c++) {
                if (c < 3) { CP_WAIT(1); } else { CP_WAIT(0); }
                __syncthreads();
                const uint32_t abase = sb + aBuf + c * ACH;
                const uint32_t bbase = sb + FWB + (c & 1) * 18432;
#pragma unroll
                for (int kc = 0; kc < 64; kc += 16) {
                    uint32_t a[2][4], bh[2][4];
#pragma unroll
                    for (int mt = 0; mt < 2; mt++)
                        ldsm_x4(a[mt], abase + aoff + mt * (16 * RS * 2) + kc * 2);
#pragma unroll
                    for (int p = 0; p < 2; p++)
                        ldsm_x4(bh[p], bbase + boff + p * (16 * RS * 2) + kc * 2);
#pragma unroll
                    for (int mt = 0; mt < 2; mt++)
#pragma unroll
                        for (int q = 0; q < 4; q++)
                            mma16816(acc[mt][q], a[mt], bh[q >> 1][q & 1], bh[q >> 1][(q & 1) + 2]);
                }
                __syncthreads();
                if (c + 2 < 4) {
#pragma unroll
                    for (int t = 0; t < 4; t++) {
                        const int row = lr + t * 32;
                        cpasync16(sb + FWB + (c & 1) * 18432 + (uint32_t)(row * RS + lc) * 2,
                                  Wp + (size_t)row * 256 + (c + 2) * 64 + lc);
                    }
                    CP_COMMIT();
                }
            }

            if (stage < 2) {
                const float* bp = ((stage == 0) ? bv1 : bv2) + (size_t)v * 256;
                __half* ob = reinterpret_cast<__half*>(sm) + (oBuf >> 1);
#pragma unroll
                for (int mt = 0; mt < 2; mt++) {
#pragma unroll
                    for (int q = 0; q < 4; q++) {
                        const int m = wm * 32 + mt * 16 + gid;
                        const int gn = np * 128 + wn * 32 + q * 8 + tig * 2;
                        const float b0 = bp[gn], b1 = bp[gn + 1];
                        float x0 = acc[mt][q][0] + b0, x1 = acc[mt][q][1] + b1;
                        float y0 = acc[mt][q][2] + b0, y1 = acc[mt][q][3] + b1;
                        if (stage == 0) {
                            x0 = (x0 > 0.f) ? x0 : expm1f(x0);
                            x1 = (x1 > 0.f) ? x1 : expm1f(x1);
                            y0 = (y0 > 0.f) ? y0 : expm1f(y0);
                            y1 = (y1 > 0.f) ? y1 : expm1f(y1);
                        }
                        const int ch = gn >> 6;
                        const int ko = gn & 63;
                        __half* d0 = ob + ch * (ACH / 2) + m * RS + ko;
                        *reinterpret_cast<__half2*>(d0) = __floats2half2_rn(x0, x1);
                        *reinterpret_cast<__half2*>(d0 + 8 * RS) = __floats2half2_rn(y0, y1);
                    }
                }
                __syncthreads();
            } else {
                const float* bp = bv3 + (size_t)v * 512;
                const int jbase = np * 64;
                __half* Eg = reinterpret_cast<__half*>(sm) + (FA1 >> 1);
#pragma unroll
                for (int mt = 0; mt < 2; mt++) {
#pragma unroll
                    for (int q = 0; q < 4; q++) {
                        const int nl = wn * 32 + q * 8 + tig * 2;
                        const int jl = nl >> 1;
                        const int jg = jbase + jl;
                        const float ba = bp[jg], bb = bp[jg + 256];
                        const int r0 = wm * 32 + mt * 16 + gid;
                        float a0 = acc[mt][q][0] + ba, b0 = acc[mt][q][1] + bb;
                        float a1 = acc[mt][q][2] + ba, b1 = acc[mt][q][3] + bb;
                        Eg[r0 * 64 + jl]       = __float2half_rn(a0 * (1.f / (1.f + expf(-b0))));
                        Eg[(r0 + 8) * 64 + jl] = __float2half_rn(a1 * (1.f / (1.f + expf(-b1))));
                    }
                }
                __syncthreads();
                const int row = tid >> 2;
                const int chh = (tid & 3) * 16;
                const __half* src = Eg + row * 64 + chh;
                const __half* xsrc = VH + (size_t)(m0 + row) * DIN + v * 256 + jbase + chh;
                __half* dst = E + ((size_t)v * BT_TOK + m0 + row) * 256 + jbase + chh;
#pragma unroll
                for (int u = 0; u < 2; u++) {
                    uint4 ev = *reinterpret_cast<const uint4*>(src + u * 8);
                    uint4 xv = *reinterpret_cast<const uint4*>(xsrc + u * 8);
                    uint4 ov;
                    ov.x = hadd2_f32(ev.x, xv.x);
                    ov.y = hadd2_f32(ev.y, xv.y);
                    ov.z = hadd2_f32(ev.z, xv.z);
                    ov.w = hadd2_f32(ev.w, xv.w);
                    *reinterpret_cast<uint4*>(dst + u * 8) = ov;
                }
                __syncthreads();
            }
        }
    }
}

// ---- mega kernel: [0,256) G1, [256,1280) skip, [1280,5376) fused ----
__global__ __launch_bounds__(256, 2)
void mega_kernel(const __half* __restrict__ VH,
                 const __half* __restrict__ G1T, const float* __restrict__ bg1,
                 __half* __restrict__ H1,
                 const float* __restrict__ Wgs, const float* __restrict__ bgs,
                 float* __restrict__ SKP,
                 const __half* __restrict__ W1T, const __half* __restrict__ W2T,
                 const __half* __restrict__ W3T,
                 const float* __restrict__ bv1, const float* __restrict__ bv2,
                 const float* __restrict__ bv3, __half* __restrict__ E)
{
    extern __shared__ __align__(1024) unsigned char sm[];
    const uint32_t sb = smem_u32(sm);
    const int b = blockIdx.x;
    if (b < 256) {
        dev_g1(sm, sb, VH, G1T, bg1, H1, b);
    } else if (b < 1280) {
        dev_skip(sm, VH, Wgs, bgs, SKP, b - 256);
    } else {
        dev_fused(sm, sb, VH, W1T, W2T, W3T, bv1, bv2, bv3, E, b - 1280);
    }
}

// ---------------------------------------------------------------------------
// tail_kernel: per block (64 tokens): h2 = H1@G2T+bg2 (smem) -> wlogits ->
// enc combine over E. Replaces G2 + wlogits + enc_combine.
// smem: phase1: A 4x9216 @0, B dbl 2x36864 @36864 (110592).
//       phase2/3: H2s fp32 [64][256] @0 (65536), Ws Wg3 @65536 (32768),
//                 sws [64][16] @98304 (4096).
// ---------------------------------------------------------------------------
__global__ __launch_bounds__(256, 2)
void tail_kernel(const __half* __restrict__ H1, const __half* __restrict__ G2T,
                 const float* __restrict__ bg2,
                 const float* __restrict__ Wg3, const float* __restrict__ bg3,
                 const float* __restrict__ gg, const float* __restrict__ bgn,
                 const float* __restrict__ SKP, const __half* __restrict__ E,
                 const float* __restrict__ gv, const float* __restrict__ bvn,
                 float* __restrict__ outp, float* __restrict__ wout)
{
    extern __shared__ __align__(1024) unsigned char sm[];
    const uint32_t sb = smem_u32(sm);
    const int tid = threadIdx.x;
    const int lane = tid & 31, wid = tid >> 5;
    const int wm = wid & 1, wn = wid >> 1;
    const int gid = lane >> 2, tig = lane & 3;
    const long t0 = (long)blockIdx.x * 64;

    // ---- phase 1: GEMM h2[64,256] = H1[t0:,256] @ G2T^T ----
    {
        const __half* ap = H1 + (size_t)t0 * 256;
#pragma unroll
        for (int t = 0; t < 8; t++) {
            const int id = tid + t * 256;
            const int ch = id >> 9;
            const int rem = id & 511;
            const int row = rem >> 3;
            const int lc8 = (rem & 7) * 8;
            cpasync16(sb + ch * ACH + (uint32_t)(row * RS + lc8) * 2,
                      ap + (size_t)row * 256 + ch * 64 + lc8);
        }
        CP_COMMIT();
    }
#pragma unroll
    for (int pc = 0; pc < 2; pc++) {
#pragma unroll
        for (int t = 0; t < 8; t++) {
            const int id = tid + t * 256;
            const int row = id >> 3;
            const int lc8 = (id & 7) * 8;
            cpasync16(sb + 36864 + pc * 36864 + (uint32_t)(row * RS + lc8) * 2,
                      G2T + (size_t)row * 256 + pc * 64 + lc8);
        }
        CP_COMMIT();
    }

    const uint32_t aoff = (uint32_t)(((wm * 32 + (lane & 15)) * RS + (lane >> 4) * 8) * 2);
    const uint32_t boffL = (uint32_t)(((wn * 64 + (lane & 15)) * RS + (lane >> 4) * 8) * 2);

    float acc[2][8][4];
#pragma unroll
    for (int i = 0; i < 2; i++)
#pragma unroll
        for (int j = 0; j < 8; j++)
#pragma unroll
            for (int k = 0; k < 4; k++) acc[i][j][k] = 0.f;

    for (int c = 0; c < 4; c++) {
        if (c < 3) { CP_WAIT(1); } else { CP_WAIT(0); }
        __syncthreads();
        const uint32_t abase = sb + c * ACH;
        const uint32_t bbase = sb + 36864 + (c & 1) * 36864;
#pragma unroll
        for (int kc = 0; kc < 64; kc += 16) {
            uint32_t a[2][4], bh[4][4];
#pragma unroll
            for (int mt = 0; mt < 2; mt++)
                ldsm_x4(a[mt], abase + aoff + mt * (16 * RS * 2) + kc * 2);
#pragma unroll
            for (int p = 0; p < 4; p++)
                ldsm_x4(bh[p], bbase + boffL + p * (16 * RS * 2) + kc * 2);
#pragma unroll
            for (int mt = 0; mt < 2; mt++)
#pragma unroll
                for (int q = 0; q < 8; q++)
                    mma16816(acc[mt][q], a[mt], bh[q >> 1][q & 1], bh[q >> 1][(q & 1) + 2]);
        }
        __syncthreads();
        if (c + 2 < 4) {
#pragma unroll
            for (int t = 0; t < 8; t++) {
                const int id = tid + t * 256;
                const int row = id >> 3;
                const int lc8 = (id & 7) * 8;
                cpasync16(sb + 36864 + (c & 1) * 36864 + (uint32_t)(row * RS + lc8) * 2,
                          G2T + (size_t)row * 256 + (c + 2) * 64 + lc8);
            }
            CP_COMMIT();
        }
    }

    // write h2 tile into smem fp32
    float* H2s = reinterpret_cast<float*>(sm);
#pragma unroll
    for (int mt = 0; mt < 2; mt++) {
#pragma unroll
        for (int q = 0; q < 8; q++) {
            const int m = wm * 32 + mt * 16 + gid;
            const int n = wn * 64 + q * 8 + tig * 2;
            const float b0 = bg2[n], b1 = bg2[n + 1];
            H2s[m * 256 + n]           = acc[mt][q][0] + b0;
            H2s[m * 256 + n + 1]       = acc[mt][q][1] + b1;
            H2s[(m + 8) * 256 + n]     = acc[mt][q][2] + b0;
            H2s[(m + 8) * 256 + n + 1] = acc[mt][q][3] + b1;
        }
    }
    // stage Wg3
    float* Ws = reinterpret_cast<float*>(sm + 65536);
#pragma unroll
    for (int i = 0; i < 32; i++) Ws[tid + i * 256] = Wg3[tid + i * 256];
    float* sws = reinterpret_cast<float*>(sm + 98304);
    __syncthreads();

    // ---- phase 2: wlogits per token (warp per token, 8 rounds) ----
#pragma unroll
    for (int r = 0; r < 8; r++) {
        const int tl = wid + r * 8;
        const long t = t0 + tl;
        const float* h2t = H2s + tl * 256;
        float s = bg3[lane];
#pragma unroll 8
        for (int k = 0; k < 256; k += 4) {
            float4 h = *reinterpret_cast<const float4*>(h2t + k);
            s += h.x * Ws[(k + 0) * 32 + lane];
            s += h.y * Ws[(k + 1) * 32 + lane];
            s += h.z * Ws[(k + 2) * 32 + lane];
            s += h.w * Ws[(k + 3) * 32 + lane];
        }
        float bhalf = __shfl_down_sync(0xffffffffu, s, 16);
        float rr = 0.f;
        if (lane < 16)
            rr = s * (1.f / (1.f + expf(-bhalf))) + SKP[t * 16 + lane];
        float sum = rr;
        for (int m = 8; m; m >>= 1) sum += __shfl_xor_sync(0xffffffffu, sum, m, 16);
        float mean = sum * (1.f / 16.f);
        float d = rr - mean;
        float vs = d * d;
        for (int m = 8; m; m >>= 1) vs += __shfl_xor_sync(0xffffffffu, vs, m, 16);
        float rstd = rsqrtf(vs * (1.f / 16.f) + 1e-6f);
        float ln = 0.f;
        if (lane < 16) ln = d * rstd * gg[lane] + bgn[lane];
        float mx = ln;
        for (int m = 8; m; m >>= 1) mx = fmaxf(mx, __shfl_xor_sync(0xffffffffu, mx, m, 16));
        float e = (lane < 16) ? expf(ln - mx) : 0.f;
        float se = e;
        for (int m = 8; m; m >>= 1) se += __shfl_xor_sync(0xffffffffu, se, m, 16);
        if (lane < 16) {
            float wv = e / se;
            wout[t * 16 + lane] = wv;
            sws[tl * 16 + lane] = wv;
        }
    }
    __syncthreads();

    // ---- phase 3: enc combine (warp per token, 8 rounds, 16 vars) ----
    const int c0 = lane * 8;
#pragma unroll
    for (int r = 0; r < 8; r++) {
        const int tl = wid + r * 8;
        const long t = t0 + tl;
        float acc8[8];
#pragma unroll
        for (int i = 0; i < 8; i++) acc8[i] = 0.f;
#pragma unroll
        for (int v = 0; v < 16; v++) {
            uint4 rawE = *reinterpret_cast<const uint4*>(
                E + ((size_t)v * BT_TOK + t) * 256 + c0);
            const __half2* he = reinterpret_cast<const __half2*>(&rawE);
            float e[8];
#pragma unroll
            for (int i = 0; i < 4; i++) {
                float2 fe = __half22float2(he[i]);
                e[2 * i]     = fe.x;
                e[2 * i + 1] = fe.y;
            }
            float s1 = 0.f, s2 = 0.f;
#pragma unroll
            for (int i = 0; i < 8; i++) { s1 += e[i]; s2 += e[i] * e[i]; }
#pragma unroll
            for (int m = 16; m; m >>= 1) {
                s1 += __shfl_xor_sync(0xffffffffu, s1, m);
                s2 += __shfl_xor_sync(0xffffffffu, s2, m);
            }
            const float mean = s1 * (1.f / 256.f);
            const float var = s2 * (1.f / 256.f) - mean * mean;
            const float rstd = rsqrtf(var + 1e-6f);
            const float w = sws[tl * 16 + v];
            const float4 g0 = *reinterpret_cast<const float4*>(gv + v * DDIM + c0);
            const float4 g1 = *reinterpret_cast<const float4*>(gv + v * DDIM + c0 + 4);
            const float4 b0 = *reinterpret_cast<const float4*>(bvn + v * DDIM + c0);
            const float4 b1 = *reinterpret_cast<const float4*>(bvn + v * DDIM + c0 + 4);
            const float gva[8] = {g0.x, g0.y, g0.z, g0.w, g1.x, g1.y, g1.z, g1.w};
            const float bva[8] = {b0.x, b0.y, b0.z, b0.w, b1.x, b1.y, b1.z, b1.w};
#pragma unroll
            for (int i = 0; i < 8; i++)
                acc8[i] += ((e[i] - mean) * rstd * gva[i] + bva[i]) * w;
        }
        float4 o0, o1;
        o0.x = acc8[0]; o0.y = acc8[1]; o0.z = acc8[2]; o0.w = acc8[3];
        o1.x = acc8[4]; o1.y = acc8[5]; o1.z = acc8[6]; o1.w = acc8[7];
        float* dp = outp + t * DDIM + c0;
        *reinterpret_cast<float4*>(dp) = o0;
        *reinterpret_cast<float4*>(dp + 4) = o1;
    }
}

// ---------------------------------------------------------------------------
extern "C" void kernel_launch(void* const* d_in, const int* in_sizes, int n_in,
                              void* d_out, int out_size)
{
    const float* vars = (const float*)d_in[0];
    const float* Wg1  = (const float*)d_in[1];
    const float* bg1  = (const float*)d_in[2];
    const float* Wg2  = (const float*)d_in[3];
    const float* bg2  = (const float*)d_in[4];
    const float* Wg3  = (const float*)d_in[5];
    const float* bg3  = (const float*)d_in[6];
    const float* Wgs  = (const float*)d_in[7];
    const float* bgs  = (const float*)d_in[8];
    const float* gg   = (const float*)d_in[9];
    const float* bgn  = (const float*)d_in[10];
    const float* Wv1  = (const float*)d_in[11];
    const float* bv1  = (const float*)d_in[12];
    const float* Wv2  = (const float*)d_in[13];
    const float* bv2  = (const float*)d_in[14];
    const float* Wv3  = (const float*)d_in[15];
    const float* bv3  = (const float*)d_in[16];
    const float* gv   = (const float*)d_in[17];
    const float* bvn  = (const float*)d_in[18];

    float* out  = (float*)d_out;
    float* wout = out + BT_TOK * DDIM;

    unsigned char* gb = nullptr;
    cudaGetSymbolAddress((void**)&gb, g_buf);
    __half* VH  = (__half*)(gb + O_VH);
    __half* H1  = (__half*)(gb + O_H1);
    __half* E   = (__half*)(gb + O_E);
    float*  SKP = (float*)(gb + O_SKIP);
    __half* G1T = (__half*)(gb + O_G1);
    __half* G2T = (__half*)(gb + O_G2);
    __half* W1T = (__half*)(gb + O_W1);
    __half* W2T = (__half*)(gb + O_W2);
    __half* W3T = (__half*)(gb + O_W3);

    cudaFuncSetAttribute(mega_kernel, cudaFuncAttributeMaxDynamicSharedMemorySize, SMEM_TOT);
    cudaFuncSetAttribute(tail_kernel, cudaFuncAttributeMaxDynamicSharedMemorySize, SMEM_TOT);

    // all conversions in one launch (weight transposes first)
    conv_mega<<<37952, 256>>>(vars, VH, Wg1, G1T, Wg2, G2T,
                              Wv1, W1T, Wv2, W2T, Wv3, W3T);

    // mega: G1 + skip + fused per-variable chain, co-scheduled
    mega_kernel<<<5376, 256, SMEM_TOT>>>(VH, G1T, bg1, H1, Wgs, bgs, SKP,
                                         W1T, W2T, W3T, bv1, bv2, bv3, E);

    // tail: G2 GEMM + wlogits + enc combine in one launch
    tail_kernel<<<256, 256, SMEM_TOT>>>(H1, G2T, bg2, Wg3, bg3, gg, bgn,
                                        SKP, E, gv, bvn, out, wout);
}

// round 14
// speedup vs baseline: 1.0374x; 1.0374x over previous
#include <cuda_runtime.h>
#include <cuda_fp16.h>
#include <cstdint>

// ---------------------------------------------------------------------------
// VSN on GB300 — Round 14: conv_mega (R13, measured win) + R12 mega kernel +
// R12 separate tail (G2 / wlogits / enc_combine with full-width grids).
// B=8,T=2048,NV=16,D=256 -> BT=16384, DIN=4096
// ---------------------------------------------------------------------------

#define BT_TOK 16384L
#define DDIM   256
#define DIN    4096

// ---------------- scratch (bytes) ----------------
#define O_VH    0ULL            // vars fp16 [16384,4096]          128MB
#define O_H1    134217728ULL    // h1 fp16 [16384,256]
#define O_H2F   142606336ULL    // h2 fp32 [16384,256]
#define O_E     159383552ULL    // E=glu+x fp16 16x[16384,256]     128MB
#define O_SKIP  293601280ULL    // skip fp32 [16384,16]
#define O_G1    294649856ULL    // Wg1^T fp16 [256,4096]
#define O_G2    296747008ULL    // Wg2^T fp16 [256,256]
#define O_W1    296878080ULL    // Wv1^T fp16 16x[256,256]
#define O_W2    298975232ULL
#define O_W3    301072384ULL    // Wv3^T perm fp16 16x[512,256]
#define G_TOTAL 305266688ULL

__device__ __align__(1024) unsigned char g_buf[G_TOTAL];

// ---------------- helpers ----------------
__device__ __forceinline__ uint32_t smem_u32(const void* p) {
    uint32_t a;
    asm("{ .reg .u64 t; cvta.to.shared.u64 t, %1; cvt.u32.u64 %0, t; }" : "=r"(a) : "l"(p));
    return a;
}
__device__ __forceinline__ void cpasync16(uint32_t dst, const void* src) {
    asm volatile("cp.async.cg.shared.global [%0], [%1], 16;" :: "r"(dst), "l"(src));
}
#define CP_COMMIT() asm volatile("cp.async.commit_group;" ::: "memory")
#define CP_WAIT(n)  asm volatile("cp.async.wait_group %0;" :: "n"(n) : "memory")

__device__ __forceinline__ void ldsm_x4(uint32_t (&r)[4], uint32_t addr) {
    asm volatile("ldmatrix.sync.aligned.m8n8.x4.shared.b16 {%0,%1,%2,%3}, [%4];"
        : "=r"(r[0]), "=r"(r[1]), "=r"(r[2]), "=r"(r[3]) : "r"(addr));
}
__device__ __forceinline__ void mma16816(float (&c)[4], const uint32_t (&a)[4],
                                         uint32_t b0, uint32_t b1) {
    asm volatile("mma.sync.aligned.m16n8k16.row.col.f32.f16.f16.f32 "
        "{%0,%1,%2,%3}, {%4,%5,%6,%7}, {%8,%9}, {%0,%1,%2,%3};"
        : "+f"(c[0]), "+f"(c[1]), "+f"(c[2]), "+f"(c[3])
        : "r"(a[0]), "r"(a[1]), "r"(a[2]), "r"(a[3]), "r"(b0), "r"(b1));
}
__device__ __forceinline__ uint32_t hadd2_f32(uint32_t e, uint32_t x) {
    __half2 he = *reinterpret_cast<__half2*>(&e);
    __half2 hx = *reinterpret_cast<__half2*>(&x);
    float2 fe = __half22float2(he);
    float2 fx = __half22float2(hx);
    __half2 r = __floats2half2_rn(fe.x + fx.x, fe.y + fx.y);
    return *reinterpret_cast<uint32_t*>(&r);
}

// ---------------------------------------------------------------------------
// conv_mega: all conversions in one launch.
// [0,64) G2T, [64,1088) G1T, [1088,2112) W1T, [2112,3136) W2T,
// [3136,5184) W3T(perm), [5184,37952) conv_split
// ---------------------------------------------------------------------------
__device__ __noinline__ void dev_wT(const float* W, __half* TH, int K, int N,
                                    int bx, int by, int bz, float (*tile)[33])
{
    const size_t vb = (size_t)bz * K * N;
    const int k0 = by * 32, n0 = bx * 32;
    const int tx = threadIdx.x & 31, ty = threadIdx.x >> 5;
#pragma unroll
    for (int i = 0; i < 4; i++)
        tile[ty + i * 8][tx] = W[vb + (size_t)(k0 + ty + i * 8) * N + n0 + tx];
    __syncthreads();
#pragma unroll
    for (int i = 0; i < 4; i++) {
        int n = ty + i * 8;
        TH[vb + (size_t)(n0 + n) * K + k0 + tx] = __float2half_rn(tile[tx][n]);
    }
}

__device__ __noinline__ void dev_wT3(const float* W, __half* TH,
                                     int bx, int by, int bz, float (*tile)[33])
{
    const size_t vbs = (size_t)bz * 256 * 512;
    const size_t vbd = (size_t)bz * 512 * 256;
    const int k0 = by * 32, c0 = bx * 32;
    const int tx = threadIdx.x & 31, ty = threadIdx.x >> 5;
#pragma unroll
    for (int i = 0; i < 4; i++)
        tile[ty + i * 8][tx] = W[vbs + (size_t)(k0 + ty + i * 8) * 512 + c0 + tx];
    __syncthreads();
#pragma unroll
    for (int i = 0; i < 4; i++) {
        int c = c0 + ty + i * 8;
        int orow = (c < 256) ? (2 * c) : (2 * (c - 256) + 1);
        TH[vbd + (size_t)orow * 256 + k0 + tx] = __float2half_rn(tile[tx][ty + i * 8]);
    }
}

__device__ __noinline__ void dev_split(const float* x, __half* h, int bidx)
{
    size_t i = ((size_t)bidx * 512 + threadIdx.x * 2) * 4;
#pragma unroll
    for (int u = 0; u < 2; u++) {
        float4 v = *reinterpret_cast<const float4*>(x + i + u * 4);
        *reinterpret_cast<__half2*>(h + i + u * 4)     = __floats2half2_rn(v.x, v.y);
        *reinterpret_cast<__half2*>(h + i + u * 4 + 2) = __floats2half2_rn(v.z, v.w);
    }
}

__global__ __launch_bounds__(256)
void conv_mega(const float* __restrict__ vars, __half* __restrict__ VH,
               const float* __restrict__ Wg1, __half* __restrict__ G1T,
               const float* __restrict__ Wg2, __half* __restrict__ G2T,
               const float* __restrict__ Wv1, __half* __restrict__ W1T,
               const float* __restrict__ Wv2, __half* __restrict__ W2T,
               const float* __restrict__ Wv3, __half* __restrict__ W3T)
{
    __shared__ float tile[32][33];
    const int b = blockIdx.x;
    if (b < 64) {
        dev_wT(Wg2, G2T, 256, 256, b & 7, b >> 3, 0, tile);
    } else if (b < 1088) {
        int i = b - 64;  dev_wT(Wg1, G1T, 4096, 256, i & 7, i >> 3, 0, tile);
    } else if (b < 2112) {
        int i = b - 1088; dev_wT(Wv1, W1T, 256, 256, i & 7, (i >> 3) & 7, i >> 6, tile);
    } else if (b < 3136) {
        int i = b - 2112; dev_wT(Wv2, W2T, 256, 256, i & 7, (i >> 3) & 7, i >> 6, tile);
    } else if (b < 5184) {
        int i = b - 3136; dev_wT3(Wv3, W3T, i & 15, (i >> 4) & 7, i >> 7, tile);
    } else {
        dev_split(vars, VH, b - 5184);
    }
}

// ---------------------------------------------------------------------------
#define RS 72
#define OFF_B  18432
#define ST_SIZE 36864
#define SMEM_TOT 110592

#define ACH 9216u
#define FA0 0u
#define FA1 36864u
#define FWB 73728u

// ---- G1 GEMM body (ELU + fp16 out). K=4096, bidx in [0,256) ----
__device__ __noinline__ void dev_g1(unsigned char* sm, uint32_t sb,
                                    const __half* VH, const __half* G1T,
                                    const float* bg1, __half* H1, int bidx)
{
    const int tid = threadIdx.x;
    const int lane = tid & 31, wid = tid >> 5;
    const int wm = wid & 1, wn = wid >> 1;
    const int nb = (bidx & 1) * 128;
    const int m0 = (bidx >> 1) * 128;

    const __half* Ap  = VH + (size_t)m0 * DIN;
    const __half* Bhp = G1T + (size_t)nb * DIN;
    const int lr = tid >> 3;
    const int lc = (tid & 7) * 8;

    float acc[4][4][4];
#pragma unroll
    for (int i = 0; i < 4; i++)
#pragma unroll
        for (int j = 0; j < 4; j++)
#pragma unroll
            for (int k = 0; k < 4; k++) acc[i][j][k] = 0.f;

    auto load_stage = [&](int s, int k0) {
        const uint32_t base = sb + s * ST_SIZE;
#pragma unroll
        for (int t = 0; t < 4; t++) {
            const int row = lr + t * 32;
            const uint32_t doff = (uint32_t)(row * RS + lc) * 2;
            cpasync16(base + doff,         Ap  + (size_t)row * DIN + k0 + lc);
            cpasync16(base + OFF_B + doff, Bhp + (size_t)row * DIN + k0 + lc);
        }
    };

    const uint32_t aoff = (uint32_t)(((wm * 64 + (lane & 15)) * RS + (lane >> 4) * 8) * 2);
    const uint32_t boff = (uint32_t)(((wn * 32 + (lane & 15)) * RS + (lane >> 4) * 8) * 2);

    load_stage(0, 0);  CP_COMMIT();
    load_stage(1, 64); CP_COMMIT();

    int sidx = 0;
    for (int c = 0; c < 64; c++) {
        CP_WAIT(1);
        __syncthreads();
        const uint32_t base = sb + sidx * ST_SIZE;
#pragma unroll
        for (int kc = 0; kc < 64; kc += 16) {
            uint32_t a[4][4], bh[2][4];
#pragma unroll
            for (int mt = 0; mt < 4; mt++)
                ldsm_x4(a[mt], base + aoff + mt * (16 * RS * 2) + kc * 2);
#pragma unroll
            for (int p = 0; p < 2; p++)
                ldsm_x4(bh[p], base + OFF_B + boff + p * (16 * RS * 2) + kc * 2);
#pragma unroll
            for (int mt = 0; mt < 4; mt++)
#pragma unroll
                for (int q = 0; q < 4; q++)
                    mma16816(acc[mt][q], a[mt], bh[q >> 1][q & 1], bh[q >> 1][(q & 1) + 2]);
        }
        __syncthreads();
        if (c + 2 < 64) {
            int ns = sidx + 2; if (ns >= 3) ns -= 3;
            load_stage(ns, (c + 2) * 64);
        }
        CP_COMMIT();
        if (++sidx == 3) sidx = 0;
    }

    const int gid = lane >> 2, tig = lane & 3;
#pragma unroll
    for (int mt = 0; mt < 4; mt++) {
#pragma unroll
        for (int q = 0; q < 4; q++) {
            const int m = m0 + wm * 64 + mt * 16 + gid;
            const int n = nb + wn * 32 + q * 8 + tig * 2;
            const float b0 = bg1[n], b1 = bg1[n + 1];
            float x0 = acc[mt][q][0] + b0, x1 = acc[mt][q][1] + b1;
            float y0 = acc[mt][q][2] + b0, y1 = acc[mt][q][3] + b1;
            x0 = (x0 > 0.f) ? x0 : expm1f(x0);
            x1 = (x1 > 0.f) ? x1 : expm1f(x1);
            y0 = (y0 > 0.f) ? y0 : expm1f(y0);
            y1 = (y1 > 0.f) ? y1 : expm1f(y1);
            __half* d0 = H1 + (size_t)m * 256 + n;
            *reinterpret_cast<__half2*>(d0) = __floats2half2_rn(x0, x1);
            *reinterpret_cast<__half2*>(d0 + 8 * 256) = __floats2half2_rn(y0, y1);
        }
    }
}

// ---- skip body: bidx in [0,1024) ----
__device__ __noinline__ void dev_skip(unsigned char* sm,
                                      const __half* vh, const float* Wgs,
                                      const float* bgs, float* skipOut, int bidx)
{
    __half (*As)[256] = reinterpret_cast<__half (*)[256]>(sm);
    float (*Ws)[16]  = reinterpret_cast<float (*)[16]>(sm + 8192);
    const int tid = threadIdx.x;
    const long t0 = (long)bidx * 16;
    const int o = tid & 15;
    const int tr = tid >> 4;
    float s = 0.f;
    for (int k0 = 0; k0 < DIN; k0 += 256) {
        {
            const int r = tid >> 4;
            const int cc = (tid & 15) * 16;
            *reinterpret_cast<uint4*>(&As[r][cc]) =
                *reinterpret_cast<const uint4*>(vh + (t0 + r) * DIN + k0 + cc);
            *reinterpret_cast<uint4*>(&As[r][cc + 8]) =
                *reinterpret_cast<const uint4*>(vh + (t0 + r) * DIN + k0 + cc + 8);
        }
        {
            const int r = tid;
            *reinterpret_cast<float4*>(&Ws[r][0])  = *reinterpret_cast<const float4*>(Wgs + (long)(k0 + r) * 16 + 0);
            *reinterpret_cast<float4*>(&Ws[r][4])  = *reinterpret_cast<const float4*>(Wgs + (long)(k0 + r) * 16 + 4);
            *reinterpret_cast<float4*>(&Ws[r][8])  = *reinterpret_cast<const float4*>(Wgs + (long)(k0 + r) * 16 + 8);
            *reinterpret_cast<float4*>(&Ws[r][12]) = *reinterpret_cast<const float4*>(Wgs + (long)(k0 + r) * 16 + 12);
        }
        __syncthreads();
#pragma unroll 16
        for (int kk = 0; kk < 256; kk++) s += __half2float(As[tr][kk]) * Ws[kk][o];
        __syncthreads();
    }
    skipOut[(t0 + tr) * 16 + o] = s + bgs[o];
}

// ---- fused per-variable chain body: bidx in [0,4096) ----
__device__ __noinline__ void dev_fused(unsigned char* sm, uint32_t sb,
                                       const __half* VH,
                                       const __half* W1T, const __half* W2T,
                                       const __half* W3T,
                                       const float* bv1, const float* bv2,
                                       const float* bv3, __half* E, int bidx)
{
    const int tid = threadIdx.x;
    const int lane = tid & 31, wid = tid >> 5;
    const int wm = wid & 1, wn = wid >> 1;
    const int gid = lane >> 2, tig = lane & 3;
    const int v = bidx >> 8;
    const int m0 = (bidx & 255) * 64;

    {
        const __half* xp = VH + (size_t)m0 * DIN + v * 256;
#pragma unroll
        for (int t = 0; t < 8; t++) {
            const int id = tid + t * 256;
            const int ch = id >> 9;
            const int rem = id & 511;
            const int row = rem >> 3;
            const int lc8 = (rem & 7) * 8;
            cpasync16(sb + FA0 + ch * ACH + (uint32_t)(row * RS + lc8) * 2,
                      xp + (size_t)row * DIN + ch * 64 + lc8);
        }
        CP_COMMIT();
    }

    const uint32_t aoff = (uint32_t)(((wm * 32 + (lane & 15)) * RS + (lane >> 4) * 8) * 2);
    const uint32_t boff = (uint32_t)(((wn * 32 + (lane & 15)) * RS + (lane >> 4) * 8) * 2);
    const int lr = tid >> 3;
    const int lc = (tid & 7) * 8;

    for (int stage = 0; stage < 3; stage++) {
        const __half* W = (stage == 0) ? (W1T + (size_t)v * 65536)
                        : (stage == 1) ? (W2T + (size_t)v * 65536)
                                       : (W3T + (size_t)v * 131072);
        const int nPass = (stage == 2) ? 4 : 2;
        const uint32_t aBuf = (stage == 1) ? FA1 : FA0;
        const uint32_t oBuf = (stage == 0) ? FA1 : FA0;

        for (int np = 0; np < nPass; np++) {
            float acc[2][4][4];
#pragma unroll
            for (int i = 0; i < 2; i++)
#pragma unroll
                for (int j = 0; j < 4; j++)
#pragma unroll
                    for (int k = 0; k < 4; k++) acc[i][j][k] = 0.f;

            const __half* Wp = W + (size_t)(np * 128) * 256;
#pragma unroll
            for (int pc = 0; pc < 2; pc++) {
#pragma unroll
                for (int t = 0; t < 4; t++) {
                    const int row = lr + t * 32;
                    cpasync16(sb + FWB + pc * 18432 + (uint32_t)(row * RS + lc) * 2,
                              Wp + (size_t)row * 256 + pc * 64 + lc);
                }
                CP_COMMIT();
            }

            for (int c = 0; c < 4; c++) {
                if (c < 3) { CP_WAIT(1); } else { CP_WAIT(0); }
                __syncthreads();
                const uint32_t abase = sb + aBuf + c * ACH;
                const uint32_t bbase = sb + FWB + (c & 1) * 18432;
#pragma unroll
                for (int kc = 0; kc < 64; kc += 16) {
                    uint32_t a[2][4], bh[2][4];
#pragma unroll
                    for (int mt = 0; mt < 2; mt++)
                        ldsm_x4(a[mt], abase + aoff + mt * (16 * RS * 2) + kc * 2);
#pragma unroll
                    for (int p = 0; p < 2; p++)
                        ldsm_x4(bh[p], bbase + boff + p * (16 * RS * 2) + kc * 2);
#pragma unroll
                    for (int mt = 0; mt < 2; mt++)
#pragma unroll
                        for (int q = 0; q < 4; q++)
                            mma16816(acc[mt][q], a[mt], bh[q >> 1][q & 1], bh[q >> 1][(q & 1) + 2]);
                }
                __syncthreads();
                if (c + 2 < 4) {
#pragma unroll
                    for (int t = 0; t < 4; t++) {
                        const int row = lr + t * 32;
                        cpasync16(sb + FWB + (c & 1) * 18432 + (uint32_t)(row * RS + lc) * 2,
                                  Wp + (size_t)row * 256 + (c + 2) * 64 + lc);
                    }
                    CP_COMMIT();
                }
            }

            if (stage < 2) {
                const float* bp = ((stage == 0) ? bv1 : bv2) + (size_t)v * 256;
                __half* ob = reinterpret_cast<__half*>(sm) + (oBuf >> 1);
#pragma unroll
                for (int mt = 0; mt < 2; mt++) {
#pragma unroll
                    for (int q = 0; q < 4; q++) {
                        const int m = wm * 32 + mt * 16 + gid;
                        const int gn = np * 128 + wn * 32 + q * 8 + tig * 2;
                        const float b0 = bp[gn], b1 = bp[gn + 1];
                        float x0 = acc[mt][q][0] + b0, x1 = acc[mt][q][1] + b1;
                        float y0 = acc[mt][q][2] + b0, y1 = acc[mt][q][3] + b1;
                        if (stage == 0) {
                            x0 = (x0 > 0.f) ? x0 : expm1f(x0);
                            x1 = (x1 > 0.f) ? x1 : expm1f(x1);
                            y0 = (y0 > 0.f) ? y0 : expm1f(y0);
                            y1 = (y1 > 0.f) ? y1 : expm1f(y1);
                        }
                        const int ch = gn >> 6;
                        const int ko = gn & 63;
                        __half* d0 = ob + ch * (ACH / 2) + m * RS + ko;
                        *reinterpret_cast<__half2*>(d0) = __floats2half2_rn(x0, x1);
                        *reinterpret_cast<__half2*>(d0 + 8 * RS) = __floats2half2_rn(y0, y1);
                    }
                }
                __syncthreads();
            } else {
                const float* bp = bv3 + (size_t)v * 512;
                const int jbase = np * 64;
                __half* Eg = reinterpret_cast<__half*>(sm) + (FA1 >> 1);
#pragma unroll
                for (int mt = 0; mt < 2; mt++) {
#pragma unroll
                    for (int q = 0; q < 4; q++) {
                        const int nl = wn * 32 + q * 8 + tig * 2;
                        const int jl = nl >> 1;
                        const int jg = jbase + jl;
                        const float ba = bp[jg], bb = bp[jg + 256];
                        const int r0 = wm * 32 + mt * 16 + gid;
                        float a0 = acc[mt][q][0] + ba, b0 = acc[mt][q][1] + bb;
                        float a1 = acc[mt][q][2] + ba, b1 = acc[mt][q][3] + bb;
                        Eg[r0 * 64 + jl]       = __float2half_rn(a0 * (1.f / (1.f + expf(-b0))));
                        Eg[(r0 + 8) * 64 + jl] = __float2half_rn(a1 * (1.f / (1.f + expf(-b1))));
                    }
                }
                __syncthreads();
                const int row = tid >> 2;
                const int chh = (tid & 3) * 16;
                const __half* src = Eg + row * 64 + chh;
                const __half* xsrc = VH + (size_t)(m0 + row) * DIN + v * 256 + jbase + chh;
                __half* dst = E + ((size_t)v * BT_TOK + m0 + row) * 256 + jbase + chh;
#pragma unroll
                for (int u = 0; u < 2; u++) {
                    uint4 ev = *reinterpret_cast<const uint4*>(src + u * 8);
                    uint4 xv = *reinterpret_cast<const uint4*>(xsrc + u * 8);
                    uint4 ov;
                    ov.x = hadd2_f32(ev.x, xv.x);
                    ov.y = hadd2_f32(ev.y, xv.y);
                    ov.z = hadd2_f32(ev.z, xv.z);
                    ov.w = hadd2_f32(ev.w, xv.w);
                    *reinterpret_cast<uint4*>(dst + u * 8) = ov;
                }
                __syncthreads();
            }
        }
    }
}

// ---- mega kernel: [0,256) G1, [256,1280) skip, [1280,5376) fused ----
__global__ __launch_bounds__(256, 2)
void mega_kernel(const __half* __restrict__ VH,
                 const __half* __restrict__ G1T, const float* __restrict__ bg1,
                 __half* __restrict__ H1,
                 const float* __restrict__ Wgs, const float* __restrict__ bgs,
                 float* __restrict__ SKP,
                 const __half* __restrict__ W1T, const __half* __restrict__ W2T,
                 const __half* __restrict__ W3T,
                 const float* __restrict__ bv1, const float* __restrict__ bv2,
                 const float* __restrict__ bv3, __half* __restrict__ E)
{
    extern __shared__ __align__(1024) unsigned char sm[];
    const uint32_t sb = smem_u32(sm);
    const int b = blockIdx.x;
    if (b < 256) {
        dev_g1(sm, sb, VH, G1T, bg1, H1, b);
    } else if (b < 1280) {
        dev_skip(sm, VH, Wgs, bgs, SKP, b - 256);
    } else {
        dev_fused(sm, sb, VH, W1T, W2T, W3T, bv1, bv2, bv3, E, b - 1280);
    }
}

// ---------------------------------------------------------------------------
// mma_gemm for G2 (fp32 out, K=256)
// ---------------------------------------------------------------------------
__global__ __launch_bounds__(256, 2)
void mma_gemm(const __half* __restrict__ A, int lda,
              const __half* __restrict__ BH,
              const float* __restrict__ bias,
              float* __restrict__ CF, int ldc, int K)
{
    extern __shared__ __align__(1024) unsigned char sm[];
    const uint32_t sb = smem_u32(sm);
    const int tid = threadIdx.x;
    const int lane = tid & 31, wid = tid >> 5;
    const int wm = wid & 1, wn = wid >> 1;
    const int m0 = blockIdx.y * 128;
    const int nb = blockIdx.x * 128;

    const __half* Ap  = A + (size_t)m0 * lda;
    const __half* Bhp = BH + (size_t)nb * K;
    const int lr = tid >> 3;
    const int lc = (tid & 7) * 8;

    float acc[4][4][4];
#pragma unroll
    for (int i = 0; i < 4; i++)
#pragma unroll
        for (int j = 0; j < 4; j++)
#pragma unroll
            for (int k = 0; k < 4; k++) acc[i][j][k] = 0.f;

    const int nc = K >> 6;

    auto load_stage = [&](int s, int k0) {
        const uint32_t base = sb + s * ST_SIZE;
#pragma unroll
        for (int t = 0; t < 4; t++) {
            const int row = lr + t * 32;
            const uint32_t doff = (uint32_t)(row * RS + lc) * 2;
            cpasync16(base + doff,         Ap  + (size_t)row * lda + k0 + lc);
            cpasync16(base + OFF_B + doff, Bhp + (size_t)row * K   + k0 + lc);
        }
    };

    const uint32_t aoff = (uint32_t)(((wm * 64 + (lane & 15)) * RS + (lane >> 4) * 8) * 2);
    const uint32_t boff = (uint32_t)(((wn * 32 + (lane & 15)) * RS + (lane >> 4) * 8) * 2);

    load_stage(0, 0);              CP_COMMIT();
    if (nc > 1) { load_stage(1, 64); } CP_COMMIT();

    int sidx = 0;
    for (int c = 0; c < nc; c++) {
        CP_WAIT(1);
        __syncthreads();
        const uint32_t base = sb + sidx * ST_SIZE;
#pragma unroll
        for (int kc = 0; kc < 64; kc += 16) {
            uint32_t a[4][4], bh[2][4];
#pragma unroll
            for (int mt = 0; mt < 4; mt++)
                ldsm_x4(a[mt], base + aoff + mt * (16 * RS * 2) + kc * 2);
#pragma unroll
            for (int p = 0; p < 2; p++)
                ldsm_x4(bh[p], base + OFF_B + boff + p * (16 * RS * 2) + kc * 2);
#pragma unroll
            for (int mt = 0; mt < 4; mt++)
#pragma unroll
                for (int q = 0; q < 4; q++)
                    mma16816(acc[mt][q], a[mt], bh[q >> 1][q & 1], bh[q >> 1][(q & 1) + 2]);
        }
        __syncthreads();
        if (c + 2 < nc) {
            int ns = sidx + 2; if (ns >= 3) ns -= 3;
            load_stage(ns, (c + 2) * 64);
        }
        CP_COMMIT();
        if (++sidx == 3) sidx = 0;
    }

    const int gid = lane >> 2, tig = lane & 3;
#pragma unroll
    for (int mt = 0; mt < 4; mt++) {
#pragma unroll
        for (int q = 0; q < 4; q++) {
            const int m = m0 + wm * 64 + mt * 16 + gid;
            const int n = nb + wn * 32 + q * 8 + tig * 2;
            const float b0 = bias[n], b1 = bias[n + 1];
            float* d0 = CF + (size_t)m * ldc + n;
            float2 o0; o0.x = acc[mt][q][0] + b0; o0.y = acc[mt][q][1] + b1;
            float2 o1; o1.x = acc[mt][q][2] + b0; o1.y = acc[mt][q][3] + b1;
            *reinterpret_cast<float2*>(d0) = o0;
            *reinterpret_cast<float2*>(d0 + 8 * ldc) = o1;
        }
    }
}

// ---------------------------------------------------------------------------
// weight logits -> softmax weights
// ---------------------------------------------------------------------------
__global__ __launch_bounds__(256)
void wlogits_kernel(const float* __restrict__ h2, const float* __restrict__ Wg3,
                    const float* __restrict__ bg3, const float* __restrict__ gg,
                    const float* __restrict__ bgn, const float* __restrict__ skipIn,
                    float* __restrict__ wout)
{
    __shared__ float Ws[256 * 32];
    const int tid = threadIdx.x;
    const int lane = tid & 31;
#pragma unroll
    for (int i = 0; i < 32; i++) Ws[tid + i * 256] = Wg3[tid + i * 256];
    __syncthreads();

    const long t = (long)blockIdx.x * 8 + (tid >> 5);
    const float* h2t = h2 + t * 256;
    float s = bg3[lane];
#pragma unroll 8
    for (int k = 0; k < 256; k += 4) {
        float4 h = *reinterpret_cast<const float4*>(h2t + k);
        s += h.x * Ws[(k + 0) * 32 + lane];
        s += h.y * Ws[(k + 1) * 32 + lane];
        s += h.z * Ws[(k + 2) * 32 + lane];
        s += h.w * Ws[(k + 3) * 32 + lane];
    }
    float bhalf = __shfl_down_sync(0xffffffffu, s, 16);
    float r = 0.f;
    if (lane < 16)
        r = s * (1.f / (1.f + expf(-bhalf))) + skipIn[t * 16 + lane];
    float sum = r;
    for (int m = 8; m; m >>= 1) sum += __shfl_xor_sync(0xffffffffu, sum, m, 16);
    float mean = sum * (1.f / 16.f);
    float d = r - mean;
    float vs = d * d;
    for (int m = 8; m; m >>= 1) vs += __shfl_xor_sync(0xffffffffu, vs, m, 16);
    float rstd = rsqrtf(vs * (1.f / 16.f) + 1e-6f);
    float ln = 0.f;
    if (lane < 16) ln = d * rstd * gg[lane] + bgn[lane];
    float mx = ln;
    for (int m = 8; m; m >>= 1) mx = fmaxf(mx, __shfl_xor_sync(0xffffffffu, mx, m, 16));
    float e = (lane < 16) ? expf(ln - mx) : 0.f;
    float se = e;
    for (int m = 8; m; m >>= 1) se += __shfl_xor_sync(0xffffffffu, se, m, 16);
    if (lane < 16) wout[t * 16 + lane] = e / se;
}

// ---------------------------------------------------------------------------
// out = sum_v LN(E[v]) * weight[v]    (E already = glu + x)
// ---------------------------------------------------------------------------
__global__ __launch_bounds__(256)
void enc_combine_kernel(const __half* __restrict__ E, const float* __restrict__ wout,
                        const float* __restrict__ gv, const float* __restrict__ bvn,
                        float* __restrict__ outp)
{
    const long t = blockIdx.x;
    const int tid = threadIdx.x;
    const int lane = tid & 31, wid = tid >> 5;
    __shared__ float sw[16];
    __shared__ float part[8][256];
    if (tid < 16) sw[tid] = wout[t * 16 + tid];
    __syncthreads();

    const int c0 = lane * 8;
    float acc[8];
#pragma unroll
    for (int i = 0; i < 8; i++) acc[i] = 0.f;

#pragma unroll
    for (int vi = 0; vi < 2; vi++) {
        const int v = wid * 2 + vi;
        uint4 rawE = *reinterpret_cast<const uint4*>(
            E + ((size_t)v * BT_TOK + t) * 256 + c0);
        const __half2* he = reinterpret_cast<const __half2*>(&rawE);
        float e[8];
#pragma unroll
        for (int i = 0; i < 4; i++) {
            float2 fe = __half22float2(he[i]);
            e[2 * i]     = fe.x;
            e[2 * i + 1] = fe.y;
        }
        float s1 = 0.f, s2 = 0.f;
#pragma unroll
        for (int i = 0; i < 8; i++) { s1 += e[i]; s2 += e[i] * e[i]; }
#pragma unroll
        for (int m = 16; m; m >>= 1) {
            s1 += __shfl_xor_sync(0xffffffffu, s1, m);
            s2 += __shfl_xor_sync(0xffffffffu, s2, m);
        }
        const float mean = s1 * (1.f / 256.f);
        const float var = s2 * (1.f / 256.f) - mean * mean;
        const float rstd = rsqrtf(var + 1e-6f);
        const float w = sw[v];
        const float4 g0 = *reinterpret_cast<const float4*>(gv + v * DDIM + c0);
        const float4 g1 = *reinterpret_cast<const float4*>(gv + v * DDIM + c0 + 4);
        const float4 b0 = *reinterpret_cast<const float4*>(bvn + v * DDIM + c0);
        const float4 b1 = *reinterpret_cast<const float4*>(bvn + v * DDIM + c0 + 4);
        const float gva[8] = {g0.x, g0.y, g0.z, g0.w, g1.x, g1.y, g1.z, g1.w};
        const float bva[8] = {b0.x, b0.y, b0.z, b0.w, b1.x, b1.y, b1.z, b1.w};
#pragma unroll
        for (int i = 0; i < 8; i++)
            acc[i] += ((e[i] - mean) * rstd * gva[i] + bva[i]) * w;
    }
#pragma unroll
    for (int i = 0; i < 8; i++) part[wid][c0 + i] = acc[i];
    __syncthreads();
    float s = 0.f;
#pragma unroll
    for (int wwi = 0; wwi < 8; wwi++) s += part[wwi][tid];
    outp[t * DDIM + tid] = s;
}

// ---------------------------------------------------------------------------
extern "C" void kernel_launch(void* const* d_in, const int* in_sizes, int n_in,
                              void* d_out, int out_size)
{
    const float* vars = (const float*)d_in[0];
    const float* Wg1  = (const float*)d_in[1];
    const float* bg1  = (const float*)d_in[2];
    const float* Wg2  = (const float*)d_in[3];
    const float* bg2  = (const float*)d_in[4];
    const float* Wg3  = (const float*)d_in[5];
    const float* bg3  = (const float*)d_in[6];
    const float* Wgs  = (const float*)d_in[7];
    const float* bgs  = (const float*)d_in[8];
    const float* gg   = (const float*)d_in[9];
    const float* bgn  = (const float*)d_in[10];
    const float* Wv1  = (const float*)d_in[11];
    const float* bv1  = (const float*)d_in[12];
    const float* Wv2  = (const float*)d_in[13];
    const float* bv2  = (const float*)d_in[14];
    const float* Wv3  = (const float*)d_in[15];
    const float* bv3  = (const float*)d_in[16];
    const float* gv   = (const float*)d_in[17];
    const float* bvn  = (const float*)d_in[18];

    float* out  = (float*)d_out;
    float* wout = out + BT_TOK * DDIM;

    unsigned char* gb = nullptr;
    cudaGetSymbolAddress((void**)&gb, g_buf);
    __half* VH  = (__half*)(gb + O_VH);
    __half* H1  = (__half*)(gb + O_H1);
    float*  H2F = (float*)(gb + O_H2F);
    __half* E   = (__half*)(gb + O_E);
    float*  SKP = (float*)(gb + O_SKIP);
    __half* G1T = (__half*)(gb + O_G1);
    __half* G2T = (__half*)(gb + O_G2);
    __half* W1T = (__half*)(gb + O_W1);
    __half* W2T = (__half*)(gb + O_W2);
    __half* W3T = (__half*)(gb + O_W3);

    cudaFuncSetAttribute(mega_kernel, cudaFuncAttributeMaxDynamicSharedMemorySize, SMEM_TOT);
    cudaFuncSetAttribute(mma_gemm, cudaFuncAttributeMaxDynamicSharedMemorySize, SMEM_TOT);

    // all conversions in one launch (weight transposes first)
    conv_mega<<<37952, 256>>>(vars, VH, Wg1, G1T, Wg2, G2T,
                              Wv1, W1T, Wv2, W2T, Wv3, W3T);

    // mega: G1 + skip + fused per-variable chain, co-scheduled
    mega_kernel<<<5376, 256, SMEM_TOT>>>(VH, G1T, bg1, H1, Wgs, bgs, SKP,
                                         W1T, W2T, W3T, bv1, bv2, bv3, E);

    // tail: full-width grids (R12 configuration)
    mma_gemm<<<dim3(2, 128), 256, SMEM_TOT>>>(H1, 256, G2T, bg2, H2F, 256, 256);
    wlogits_kernel<<<2048, 256>>>(H2F, Wg3, bg3, gg, bgn, SKP, wout);
    enc_combine_kernel<<<16384, 256>>>(E, wout, gv, bvn, out);
}

// round 15
// speedup vs baseline: 1.0531x; 1.0152x over previous
#include <cuda_runtime.h>
#include <cuda_fp16.h>
#include <cstdint>

// ---------------------------------------------------------------------------
// VSN on GB300 — Round 15: algebraic fusion Wfuse = Wg2@Wg3 (no activation
// between them) kills the G2 GEMM + H2F buffer; wlogits reads H1 fp16.
// conv_mega + mega + enc_combine as in R14.
// B=8,T=2048,NV=16,D=256 -> BT=16384, DIN=4096
// ---------------------------------------------------------------------------

#define BT_TOK 16384L
#define DDIM   256
#define DIN    4096

// ---------------- scratch (bytes) ----------------
#define O_VH    0ULL            // vars fp16 [16384,4096]          128MB
#define O_H1    134217728ULL    // h1 fp16 [16384,256]
#define O_E     159383552ULL    // E=glu+x fp16 16x[16384,256]     128MB
#define O_SKIP  293601280ULL    // skip fp32 [16384,16]
#define O_G1    294649856ULL    // Wg1^T fp16 [256,4096]
#define O_WF    296747008ULL    // Wfuse fp32 [256,32] + bfuse[32]
#define O_W1    296878080ULL    // Wv1^T fp16 16x[256,256]
#define O_W2    298975232ULL
#define O_W3    301072384ULL    // Wv3^T perm fp16 16x[512,256]
#define G_TOTAL 305266688ULL

__device__ __align__(1024) unsigned char g_buf[G_TOTAL];

// ---------------- helpers ----------------
__device__ __forceinline__ uint32_t smem_u32(const void* p) {
    uint32_t a;
    asm("{ .reg .u64 t; cvta.to.shared.u64 t, %1; cvt.u32.u64 %0, t; }" : "=r"(a) : "l"(p));
    return a;
}
__device__ __forceinline__ void cpasync16(uint32_t dst, const void* src) {
    asm volatile("cp.async.cg.shared.global [%0], [%1], 16;" :: "r"(dst), "l"(src));
}
#define CP_COMMIT() asm volatile("cp.async.commit_group;" ::: "memory")
#define CP_WAIT(n)  asm volatile("cp.async.wait_group %0;" :: "n"(n) : "memory")

__device__ __forceinline__ void ldsm_x4(uint32_t (&r)[4], uint32_t addr) {
    asm volatile("ldmatrix.sync.aligned.m8n8.x4.shared.b16 {%0,%1,%2,%3}, [%4];"
        : "=r"(r[0]), "=r"(r[1]), "=r"(r[2]), "=r"(r[3]) : "r"(addr));
}
__device__ __forceinline__ void mma16816(float (&c)[4], const uint32_t (&a)[4],
                                         uint32_t b0, uint32_t b1) {
    asm volatile("mma.sync.aligned.m16n8k16.row.col.f32.f16.f16.f32 "
        "{%0,%1,%2,%3}, {%4,%5,%6,%7}, {%8,%9}, {%0,%1,%2,%3};"
        : "+f"(c[0]), "+f"(c[1]), "+f"(c[2]), "+f"(c[3])
        : "r"(a[0]), "r"(a[1]), "r"(a[2]), "r"(a[3]), "r"(b0), "r"(b1));
}
__device__ __forceinline__ uint32_t hadd2_f32(uint32_t e, uint32_t x) {
    __half2 he = *reinterpret_cast<__half2*>(&e);
    __half2 hx = *reinterpret_cast<__half2*>(&x);
    float2 fe = __half22float2(he);
    float2 fx = __half22float2(hx);
    __half2 r = __floats2half2_rn(fe.x + fx.x, fe.y + fx.y);
    return *reinterpret_cast<uint32_t*>(&r);
}

// ---------------------------------------------------------------------------
// conv_mega: all conversions + Wfuse in one launch.
// [0,32) Wfuse, [32,1056) G1T, [1056,2080) W1T, [2080,3104) W2T,
// [3104,5152) W3T(perm), [5152,37920) conv_split
// ---------------------------------------------------------------------------
__device__ __noinline__ void dev_wT(const float* W, __half* TH, int K, int N,
                                    int bx, int by, int bz, float* smemf)
{
    float (*tile)[33] = reinterpret_cast<float (*)[33]>(smemf);
    const size_t vb = (size_t)bz * K * N;
    const int k0 = by * 32, n0 = bx * 32;
    const int tx = threadIdx.x & 31, ty = threadIdx.x >> 5;
#pragma unroll
    for (int i = 0; i < 4; i++)
        tile[ty + i * 8][tx] = W[vb + (size_t)(k0 + ty + i * 8) * N + n0 + tx];
    __syncthreads();
#pragma unroll
    for (int i = 0; i < 4; i++) {
        int n = ty + i * 8;
        TH[vb + (size_t)(n0 + n) * K + k0 + tx] = __float2half_rn(tile[tx][n]);
    }
}

__device__ __noinline__ void dev_wT3(const float* W, __half* TH,
                                     int bx, int by, int bz, float* smemf)
{
    float (*tile)[33] = reinterpret_cast<float (*)[33]>(smemf);
    const size_t vbs = (size_t)bz * 256 * 512;
    const size_t vbd = (size_t)bz * 512 * 256;
    const int k0 = by * 32, c0 = bx * 32;
    const int tx = threadIdx.x & 31, ty = threadIdx.x >> 5;
#pragma unroll
    for (int i = 0; i < 4; i++)
        tile[ty + i * 8][tx] = W[vbs + (size_t)(k0 + ty + i * 8) * 512 + c0 + tx];
    __syncthreads();
#pragma unroll
    for (int i = 0; i < 4; i++) {
        int c = c0 + ty + i * 8;
        int orow = (c < 256) ? (2 * c) : (2 * (c - 256) + 1);
        TH[vbd + (size_t)orow * 256 + k0 + tx] = __float2half_rn(tile[tx][ty + i * 8]);
    }
}

__device__ __noinline__ void dev_split(const float* x, __half* h, int bidx)
{
    size_t i = ((size_t)bidx * 512 + threadIdx.x * 2) * 4;
#pragma unroll
    for (int u = 0; u < 2; u++) {
        float4 v = *reinterpret_cast<const float4*>(x + i + u * 4);
        *reinterpret_cast<__half2*>(h + i + u * 4)     = __floats2half2_rn(v.x, v.y);
        *reinterpret_cast<__half2*>(h + i + u * 4 + 2) = __floats2half2_rn(v.z, v.w);
    }
}

// Wfuse[k][j] = sum_m Wg2[k][m]*Wg3[m][j]; bfuse[j] = sum_m bg2[m]*Wg3[m][j]+bg3[j]
__device__ __noinline__ void dev_wfuse(const float* Wg2, const float* Wg3,
                                       const float* bg2, const float* bg3,
                                       float* WF, int j, float* smemf)
{
    const int k = threadIdx.x;
    // stage Wg3 column j
    smemf[k] = Wg3[(size_t)k * 32 + j];
    __syncthreads();
    float s = 0.f;
    const float* wr = Wg2 + (size_t)k * 256;
#pragma unroll 8
    for (int m = 0; m < 256; m++) s += wr[m] * smemf[m];
    WF[k * 32 + j] = s;
    if (k == 0) {
        float b = bg3[j];
        for (int m = 0; m < 256; m++) b += bg2[m] * smemf[m];
        WF[256 * 32 + j] = b;   // bfuse stored after Wfuse
    }
}

__global__ __launch_bounds__(256)
void conv_mega(const float* __restrict__ vars, __half* __restrict__ VH,
               const float* __restrict__ Wg1, __half* __restrict__ G1T,
               const float* __restrict__ Wg2, const float* __restrict__ Wg3,
               const float* __restrict__ bg2, const float* __restrict__ bg3,
               float* __restrict__ WF,
               const float* __restrict__ Wv1, __half* __restrict__ W1T,
               const float* __restrict__ Wv2, __half* __restrict__ W2T,
               const float* __restrict__ Wv3, __half* __restrict__ W3T)
{
    __shared__ float smemf[32 * 33];
    const int b = blockIdx.x;
    if (b < 32) {
        dev_wfuse(Wg2, Wg3, bg2, bg3, WF, b, smemf);
    } else if (b < 1056) {
        int i = b - 32;   dev_wT(Wg1, G1T, 4096, 256, i & 7, i >> 3, 0, smemf);
    } else if (b < 2080) {
        int i = b - 1056; dev_wT(Wv1, W1T, 256, 256, i & 7, (i >> 3) & 7, i >> 6, smemf);
    } else if (b < 3104) {
        int i = b - 2080; dev_wT(Wv2, W2T, 256, 256, i & 7, (i >> 3) & 7, i >> 6, smemf);
    } else if (b < 5152) {
        int i = b - 3104; dev_wT3(Wv3, W3T, i & 15, (i >> 4) & 7, i >> 7, smemf);
    } else {
        dev_split(vars, VH, b - 5152);
    }
}

// ---------------------------------------------------------------------------
#define RS 72
#define OFF_B  18432
#define ST_SIZE 36864
#define SMEM_TOT 110592

#define ACH 9216u
#define FA0 0u
#define FA1 36864u
#define FWB 73728u

// ---- G1 GEMM body (ELU + fp16 out). K=4096, bidx in [0,256) ----
__device__ __noinline__ void dev_g1(unsigned char* sm, uint32_t sb,
                                    const __half* VH, const __half* G1T,
                                    const float* bg1, __half* H1, int bidx)
{
    const int tid = threadIdx.x;
    const int lane = tid & 31, wid = tid >> 5;
    const int wm = wid & 1, wn = wid >> 1;
    const int nb = (bidx & 1) * 128;
    const int m0 = (bidx >> 1) * 128;

    const __half* Ap  = VH + (size_t)m0 * DIN;
    const __half* Bhp = G1T + (size_t)nb * DIN;
    const int lr = tid >> 3;
    const int lc = (tid & 7) * 8;

    float acc[4][4][4];
#pragma unroll
    for (int i = 0; i < 4; i++)
#pragma unroll
        for (int j = 0; j < 4; j++)
#pragma unroll
            for (int k = 0; k < 4; k++) acc[i][j][k] = 0.f;

    auto load_stage = [&](int s, int k0) {
        const uint32_t base = sb + s * ST_SIZE;
#pragma unroll
        for (int t = 0; t < 4; t++) {
            const int row = lr + t * 32;
            const uint32_t doff = (uint32_t)(row * RS + lc) * 2;
            cpasync16(base + doff,         Ap  + (size_t)row * DIN + k0 + lc);
            cpasync16(base + OFF_B + doff, Bhp + (size_t)row * DIN + k0 + lc);
        }
    };

    const uint32_t aoff = (uint32_t)(((wm * 64 + (lane & 15)) * RS + (lane >> 4) * 8) * 2);
    const uint32_t boff = (uint32_t)(((wn * 32 + (lane & 15)) * RS + (lane >> 4) * 8) * 2);

    load_stage(0, 0);  CP_COMMIT();
    load_stage(1, 64); CP_COMMIT();

    int sidx = 0;
    for (int c = 0; c < 64; c++) {
        CP_WAIT(1);
        __syncthreads();
        const uint32_t base = sb + sidx * ST_SIZE;
#pragma unroll
        for (int kc = 0; kc < 64; kc += 16) {
            uint32_t a[4][4], bh[2][4];
#pragma unroll
            for (int mt = 0; mt < 4; mt++)
                ldsm_x4(a[mt], base + aoff + mt * (16 * RS * 2) + kc * 2);
#pragma unroll
            for (int p = 0; p < 2; p++)
                ldsm_x4(bh[p], base + OFF_B + boff + p * (16 * RS * 2) + kc * 2);
#pragma unroll
            for (int mt = 0; mt < 4; mt++)
#pragma unroll
                for (int q = 0; q < 4; q++)
                    mma16816(acc[mt][q], a[mt], bh[q >> 1][q & 1], bh[q >> 1][(q & 1) + 2]);
        }
        __syncthreads();
        if (c + 2 < 64) {
            int ns = sidx + 2; if (ns >= 3) ns -= 3;
            load_stage(ns, (c + 2) * 64);
        }
        CP_COMMIT();
        if (++sidx == 3) sidx = 0;
    }

    const int gid = lane >> 2, tig = lane & 3;
#pragma unroll
    for (int mt = 0; mt < 4; mt++) {
#pragma unroll
        for (int q = 0; q < 4; q++) {
            const int m = m0 + wm * 64 + mt * 16 + gid;
            const int n = nb + wn * 32 + q * 8 + tig * 2;
            const float b0 = bg1[n], b1 = bg1[n + 1];
            float x0 = acc[mt][q][0] + b0, x1 = acc[mt][q][1] + b1;
            float y0 = acc[mt][q][2] + b0, y1 = acc[mt][q][3] + b1;
            x0 = (x0 > 0.f) ? x0 : expm1f(x0);
            x1 = (x1 > 0.f) ? x1 : expm1f(x1);
            y0 = (y0 > 0.f) ? y0 : expm1f(y0);
            y1 = (y1 > 0.f) ? y1 : expm1f(y1);
            __half* d0 = H1 + (size_t)m * 256 + n;
            *reinterpret_cast<__half2*>(d0) = __floats2half2_rn(x0, x1);
            *reinterpret_cast<__half2*>(d0 + 8 * 256) = __floats2half2_rn(y0, y1);
        }
    }
}

// ---- skip body: bidx in [0,1024) ----
__device__ __noinline__ void dev_skip(unsigned char* sm,
                                      const __half* vh, const float* Wgs,
                                      const float* bgs, float* skipOut, int bidx)
{
    __half (*As)[256] = reinterpret_cast<__half (*)[256]>(sm);
    float (*Ws)[16]  = reinterpret_cast<float (*)[16]>(sm + 8192);
    const int tid = threadIdx.x;
    const long t0 = (long)bidx * 16;
    const int o = tid & 15;
    const int tr = tid >> 4;
    float s = 0.f;
    for (int k0 = 0; k0 < DIN; k0 += 256) {
        {
            const int r = tid >> 4;
            const int cc = (tid & 15) * 16;
            *reinterpret_cast<uint4*>(&As[r][cc]) =
                *reinterpret_cast<const uint4*>(vh + (t0 + r) * DIN + k0 + cc);
            *reinterpret_cast<uint4*>(&As[r][cc + 8]) =
                *reinterpret_cast<const uint4*>(vh + (t0 + r) * DIN + k0 + cc + 8);
        }
        {
            const int r = tid;
            *reinterpret_cast<float4*>(&Ws[r][0])  = *reinterpret_cast<const float4*>(Wgs + (long)(k0 + r) * 16 + 0);
            *reinterpret_cast<float4*>(&Ws[r][4])  = *reinterpret_cast<const float4*>(Wgs + (long)(k0 + r) * 16 + 4);
            *reinterpret_cast<float4*>(&Ws[r][8])  = *reinterpret_cast<const float4*>(Wgs + (long)(k0 + r) * 16 + 8);
            *reinterpret_cast<float4*>(&Ws[r][12]) = *reinterpret_cast<const float4*>(Wgs + (long)(k0 + r) * 16 + 12);
        }
        __syncthreads();
#pragma unroll 16
        for (int kk = 0; kk < 256; kk++) s += __half2float(As[tr][kk]) * Ws[kk][o];
        __syncthreads();
    }
    skipOut[(t0 + tr) * 16 + o] = s + bgs[o];
}

// ---- fused per-variable chain body: bidx in [0,4096) ----
__device__ __noinline__ void dev_fused(unsigned char* sm, uint32_t sb,
                                       const __half* VH,
                                       const __half* W1T, const __half* W2T,
                                       const __half* W3T,
                                       const float* bv1, const float* bv2,
                                       const float* bv3, __half* E, int bidx)
{
    const int tid = threadIdx.x;
    const int lane = tid & 31, wid = tid >> 5;
    const int wm = wid & 1, wn = wid >> 1;
    const int gid = lane >> 2, tig = lane & 3;
    const int v = bidx >> 8;
    const int m0 = (bidx & 255) * 64;

    {
        const __half* xp = VH + (size_t)m0 * DIN + v * 256;
#pragma unroll
        for (int t = 0; t < 8; t++) {
            const int id = tid + t * 256;
            const int ch = id >> 9;
            const int rem = id & 511;
            const int row = rem >> 3;
            const int lc8 = (rem & 7) * 8;
            cpasync16(sb + FA0 + ch * ACH + (uint32_t)(row * RS + lc8) * 2,
                      xp + (size_t)row * DIN + ch * 64 + lc8);
        }
        CP_COMMIT();
    }

    const uint32_t aoff = (uint32_t)(((wm * 32 + (lane & 15)) * RS + (lane >> 4) * 8) * 2);
    const uint32_t boff = (uint32_t)(((wn * 32 + (lane & 15)) * RS + (lane >> 4) * 8) * 2);
    const int lr = tid >> 3;
    const int lc = (tid & 7) * 8;

    for (int stage = 0; stage < 3; stage++) {
        const __half* W = (stage == 0) ? (W1T + (size_t)v * 65536)
                        : (stage == 1) ? (W2T + (size_t)v * 65536)
                                       : (W3T + (size_t)v * 131072);
        const int nPass = (stage == 2) ? 4 : 2;
        const uint32_t aBuf = (stage == 1) ? FA1 : FA0;
        const uint32_t oBuf = (stage == 0) ? FA1 : FA0;

        for (int np = 0; np < nPass; np++) {
            float acc[2][4][4];
#pragma unroll
            for (int i = 0; i < 2; i++)
#pragma unroll
                for (int j = 0; j < 4; j++)
#pragma unroll
                    for (int k = 0; k < 4; k++) acc[i][j][k] = 0.f;

            const __half* Wp = W + (size_t)(np * 128) * 256;
#pragma unroll
            for (int pc = 0; pc < 2; pc++) {
#pragma unroll
                for (int t = 0; t < 4; t++) {
                    const int row = lr + t * 32;
                    cpasync16(sb + FWB + pc * 18432 + (uint32_t)(row * RS + lc) * 2,
                              Wp + (size_t)row * 256 + pc * 64 + lc);
                }
                CP_COMMIT();
            }

            for (int c = 0; c < 4; c++) {
                if (c < 3) { CP_WAIT(1); } else { CP_WAIT(0); }
                __syncthreads();
                const uint32_t abase = sb + aBuf + c * ACH;
                const uint32_t bbase = sb + FWB + (c & 1) * 18432;
#pragma unroll
                for (int kc = 0; kc < 64; kc += 16) {
                    uint32_t a[2][4], bh[2][4];
#pragma unroll
                    for (int mt = 0; mt < 2; mt++)
                        ldsm_x4(a[mt], abase + aoff + mt * (16 * RS * 2) + kc * 2);
#pragma unroll
                    for (int p = 0; p < 2; p++)
                        ldsm_x4(bh[p], bbase + boff + p * (16 * RS * 2) + kc * 2);
#pragma unroll
                    for (int mt = 0; mt < 2; mt++)
#pragma unroll
                        for (int q = 0; q < 4; q++)
                            mma16816(acc[mt][q], a[mt], bh[q >> 1][q & 1], bh[q >> 1][(q & 1) + 2]);
                }
                __syncthreads();
                if (c + 2 < 4) {
#pragma unroll
                    for (int t = 0; t < 4; t++) {
                        const int row = lr + t * 32;
                        cpasync16(sb + FWB + (c & 1) * 18432 + (uint32_t)(row * RS + lc) * 2,
                                  Wp + (size_t)row * 256 + (c + 2) * 64 + lc);
                    }
                    CP_COMMIT();
                }
            }

            if (stage < 2) {
                const float* bp = ((stage == 0) ? bv1 : bv2) + (size_t)v * 256;
                __half* ob = reinterpret_cast<__half*>(sm) + (oBuf >> 1);
#pragma unroll
                for (int mt = 0; mt < 2; mt++) {
#pragma unroll
                    for (int q = 0; q < 4; q++) {
                        const int m = wm * 32 + mt * 16 + gid;
                        const int gn = np * 128 + wn * 32 + q * 8 + tig * 2;
                        const float b0 = bp[gn], b1 = bp[gn + 1];
                        float x0 = acc[mt][q][0] + b0, x1 = acc[mt][q][1] + b1;
                        float y0 = acc[mt][q][2] + b0, y1 = acc[mt][q][3] + b1;
                        if (stage == 0) {
                            x0 = (x0 > 0.f) ? x0 : expm1f(x0);
                            x1 = (x1 > 0.f) ? x1 : expm1f(x1);
                            y0 = (y0 > 0.f) ? y0 : expm1f(y0);
                            y1 = (y1 > 0.f) ? y1 : expm1f(y1);
                        }
                        const int ch = gn >> 6;
                        const int ko = gn & 63;
                        __half* d0 = ob + ch * (ACH / 2) + m * RS + ko;
                        *reinterpret_cast<__half2*>(d0) = __floats2half2_rn(x0, x1);
                        *reinterpret_cast<__half2*>(d0 + 8 * RS) = __floats2half2_rn(y0, y1);
                    }
                }
                __syncthreads();
            } else {
                const float* bp = bv3 + (size_t)v * 512;
                const int jbase = np * 64;
                __half* Eg = reinterpret_cast<__half*>(sm) + (FA1 >> 1);
#pragma unroll
                for (int mt = 0; mt < 2; mt++) {
#pragma unroll
                    for (int q = 0; q < 4; q++) {
                        const int nl = wn * 32 + q * 8 + tig * 2;
                        const int jl = nl >> 1;
                        const int jg = jbase + jl;
                        const float ba = bp[jg], bb = bp[jg + 256];
                        const int r0 = wm * 32 + mt * 16 + gid;
                        float a0 = acc[mt][q][0] + ba, b0 = acc[mt][q][1] + bb;
                        float a1 = acc[mt][q][2] + ba, b1 = acc[mt][q][3] + bb;
                        Eg[r0 * 64 + jl]       = __float2half_rn(a0 * (1.f / (1.f + expf(-b0))));
                        Eg[(r0 + 8) * 64 + jl] = __float2half_rn(a1 * (1.f / (1.f + expf(-b1))));
                    }
                }
                __syncthreads();
                const int row = tid >> 2;
                const int chh = (tid & 3) * 16;
                const __half* src = Eg + row * 64 + chh;
                const __half* xsrc = VH + (size_t)(m0 + row) * DIN + v * 256 + jbase + chh;
                __half* dst = E + ((size_t)v * BT_TOK + m0 + row) * 256 + jbase + chh;
#pragma unroll
                for (int u = 0; u < 2; u++) {
                    uint4 ev = *reinterpret_cast<const uint4*>(src + u * 8);
                    uint4 xv = *reinterpret_cast<const uint4*>(xsrc + u * 8);
                    uint4 ov;
                    ov.x = hadd2_f32(ev.x, xv.x);
                    ov.y = hadd2_f32(ev.y, xv.y);
                    ov.z = hadd2_f32(ev.z, xv.z);
                    ov.w = hadd2_f32(ev.w, xv.w);
                    *reinterpret_cast<uint4*>(dst + u * 8) = ov;
                }
                __syncthreads();
            }
        }
    }
}

// ---- mega kernel: [0,256) G1, [256,1280) skip, [1280,5376) fused ----
__global__ __launch_bounds__(256, 2)
void mega_kernel(const __half* __restrict__ VH,
                 const __half* __restrict__ G1T, const float* __restrict__ bg1,
                 __half* __restrict__ H1,
                 const float* __restrict__ Wgs, const float* __restrict__ bgs,
                 float* __restrict__ SKP,
                 const __half* __restrict__ W1T, const __half* __restrict__ W2T,
                 const __half* __restrict__ W3T,
                 const float* __restrict__ bv1, const float* __restrict__ bv2,
                 const float* __restrict__ bv3, __half* __restrict__ E)
{
    extern __shared__ __align__(1024) unsigned char sm[];
    const uint32_t sb = smem_u32(sm);
    const int b = blockIdx.x;
    if (b < 256) {
        dev_g1(sm, sb, VH, G1T, bg1, H1, b);
    } else if (b < 1280) {
        dev_skip(sm, VH, Wgs, bgs, SKP, b - 256);
    } else {
        dev_fused(sm, sb, VH, W1T, W2T, W3T, bv1, bv2, bv3, E, b - 1280);
    }
}

// ---------------------------------------------------------------------------
// weight logits -> softmax weights. h3 = h1 @ Wfuse + bfuse (fp16 h1).
// ---------------------------------------------------------------------------
__global__ __launch_bounds__(256)
void wlogits_kernel(const __half* __restrict__ h1, const float* __restrict__ WF,
                    const float* __restrict__ gg, const float* __restrict__ bgn,
                    const float* __restrict__ skipIn, float* __restrict__ wout)
{
    __shared__ float Ws[256 * 32];
    __shared__ float bf[32];
    const int tid = threadIdx.x;
    const int lane = tid & 31;
#pragma unroll
    for (int i = 0; i < 32; i++) Ws[tid + i * 256] = WF[tid + i * 256];
    if (tid < 32) bf[tid] = WF[256 * 32 + tid];
    __syncthreads();

    const long t = (long)blockIdx.x * 8 + (tid >> 5);
    const __half* h1t = h1 + t * 256;
    float s = bf[lane];
#pragma unroll 4
    for (int k = 0; k < 256; k += 8) {
        uint4 raw = *reinterpret_cast<const uint4*>(h1t + k);
        const __half2* hh = reinterpret_cast<const __half2*>(&raw);
#pragma unroll
        for (int i = 0; i < 4; i++) {
            float2 f = __half22float2(hh[i]);
            s += f.x * Ws[(k + 2 * i + 0) * 32 + lane];
            s += f.y * Ws[(k + 2 * i + 1) * 32 + lane];
        }
    }
    float bhalf = __shfl_down_sync(0xffffffffu, s, 16);
    float r = 0.f;
    if (lane < 16)
        r = s * (1.f / (1.f + expf(-bhalf))) + skipIn[t * 16 + lane];
    float sum = r;
    for (int m = 8; m; m >>= 1) sum += __shfl_xor_sync(0xffffffffu, sum, m, 16);
    float mean = sum * (1.f / 16.f);
    float d = r - mean;
    float vs = d * d;
    for (int m = 8; m; m >>= 1) vs += __shfl_xor_sync(0xffffffffu, vs, m, 16);
    float rstd = rsqrtf(vs * (1.f / 16.f) + 1e-6f);
    float ln = 0.f;
    if (lane < 16) ln = d * rstd * gg[lane] + bgn[lane];
    float mx = ln;
    for (int m = 8; m; m >>= 1) mx = fmaxf(mx, __shfl_xor_sync(0xffffffffu, mx, m, 16));
    float e = (lane < 16) ? expf(ln - mx) : 0.f;
    float se = e;
    for (int m = 8; m; m >>= 1) se += __shfl_xor_sync(0xffffffffu, se, m, 16);
    if (lane < 16) wout[t * 16 + lane] = e / se;
}

// ---------------------------------------------------------------------------
// out = sum_v LN(E[v]) * weight[v]    (E already = glu + x)
// ---------------------------------------------------------------------------
__global__ __launch_bounds__(256)
void enc_combine_kernel(const __half* __restrict__ E, const float* __restrict__ wout,
                        const float* __restrict__ gv, const float* __restrict__ bvn,
                        float* __restrict__ outp)
{
    const long t = blockIdx.x;
    const int tid = threadIdx.x;
    const int lane = tid & 31, wid = tid >> 5;
    __shared__ float sw[16];
    __shared__ float part[8][256];
    if (tid < 16) sw[tid] = wout[t * 16 + tid];
    __syncthreads();

    const int c0 = lane * 8;
    float acc[8];
#pragma unroll
    for (int i = 0; i < 8; i++) acc[i] = 0.f;

#pragma unroll
    for (int vi = 0; vi < 2; vi++) {
        const int v = wid * 2 + vi;
        uint4 rawE = *reinterpret_cast<const uint4*>(
            E + ((size_t)v * BT_TOK + t) * 256 + c0);
        const __half2* he = reinterpret_cast<const __half2*>(&rawE);
        float e[8];
#pragma unroll
        for (int i = 0; i < 4; i++) {
            float2 fe = __half22float2(he[i]);
            e[2 * i]     = fe.x;
            e[2 * i + 1] = fe.y;
        }
        float s1 = 0.f, s2 = 0.f;
#pragma unroll
        for (int i = 0; i < 8; i++) { s1 += e[i]; s2 += e[i] * e[i]; }
#pragma unroll
        for (int m = 16; m; m >>= 1) {
            s1 += __shfl_xor_sync(0xffffffffu, s1, m);
            s2 += __shfl_xor_sync(0xffffffffu, s2, m);
        }
        const float mean = s1 * (1.f / 256.f);
        const float var = s2 * (1.f / 256.f) - mean * mean;
        const float rstd = rsqrtf(var + 1e-6f);
        const float w = sw[v];
        const float4 g0 = *reinterpret_cast<const float4*>(gv + v * DDIM + c0);
        const float4 g1 = *reinterpret_cast<const float4*>(gv + v * DDIM + c0 + 4);
        const float4 b0 = *reinterpret_cast<const float4*>(bvn + v * DDIM + c0);
        const float4 b1 = *reinterpret_cast<const float4*>(bvn + v * DDIM + c0 + 4);
        const float gva[8] = {g0.x, g0.y, g0.z, g0.w, g1.x, g1.y, g1.z, g1.w};
        const float bva[8] = {b0.x, b0.y, b0.z, b0.w, b1.x, b1.y, b1.z, b1.w};
#pragma unroll
        for (int i = 0; i < 8; i++)
            acc[i] += ((e[i] - mean) * rstd * gva[i] + bva[i]) * w;
    }
#pragma unroll
    for (int i = 0; i < 8; i++) part[wid][c0 + i] = acc[i];
    __syncthreads();
    float s = 0.f;
#pragma unroll
    for (int wwi = 0; wwi < 8; wwi++) s += part[wwi][tid];
    outp[t * DDIM + tid] = s;
}

// ---------------------------------------------------------------------------
extern "C" void kernel_launch(void* const* d_in, const int* in_sizes, int n_in,
                              void* d_out, int out_size)
{
    const float* vars = (const float*)d_in[0];
    const float* Wg1  = (const float*)d_in[1];
    const float* bg1  = (const float*)d_in[2];
    const float* Wg2  = (const float*)d_in[3];
    const float* bg2  = (const float*)d_in[4];
    const float* Wg3  = (const float*)d_in[5];
    const float* bg3  = (const float*)d_in[6];
    const float* Wgs  = (const float*)d_in[7];
    const float* bgs  = (const float*)d_in[8];
    const float* gg   = (const float*)d_in[9];
    const float* bgn  = (const float*)d_in[10];
    const float* Wv1  = (const float*)d_in[11];
    const float* bv1  = (const float*)d_in[12];
    const float* Wv2  = (const float*)d_in[13];
    const float* bv2  = (const float*)d_in[14];
    const float* Wv3  = (const float*)d_in[15];
    const float* bv3  = (const float*)d_in[16];
    const float* gv   = (const float*)d_in[17];
    const float* bvn  = (const float*)d_in[18];

    float* out  = (float*)d_out;
    float* wout = out + BT_TOK * DDIM;

    unsigned char* gb = nullptr;
    cudaGetSymbolAddress((void**)&gb, g_buf);
    __half* VH  = (__half*)(gb + O_VH);
    __half* H1  = (__half*)(gb + O_H1);
    __half* E   = (__half*)(gb + O_E);
    float*  SKP = (float*)(gb + O_SKIP);
    __half* G1T = (__half*)(gb + O_G1);
    float*  WF  = (float*)(gb + O_WF);
    __half* W1T = (__half*)(gb + O_W1);
    __half* W2T = (__half*)(gb + O_W2);
    __half* W3T = (__half*)(gb + O_W3);

    cudaFuncSetAttribute(mega_kernel, cudaFuncAttributeMaxDynamicSharedMemorySize, SMEM_TOT);

    // all conversions + Wfuse in one launch
    conv_mega<<<37920, 256>>>(vars, VH, Wg1, G1T, Wg2, Wg3, bg2, bg3, WF,
                              Wv1, W1T, Wv2, W2T, Wv3, W3T);

    // mega: G1 + skip + fused per-variable chain, co-scheduled
    mega_kernel<<<5376, 256, SMEM_TOT>>>(VH, G1T, bg1, H1, Wgs, bgs, SKP,
                                         W1T, W2T, W3T, bv1, bv2, bv3, E);

    // tail: wlogits (reads H1 + Wfuse), then enc combine
    wlogits_kernel<<<2048, 256>>>(H1, WF, gg, bgn, SKP, wout);
    enc_combine_kernel<<<16384, 256>>>(E, wout, gv, bvn, out);
}

// round 17
// speedup vs baseline: 1.0534x; 1.0002x over previous
#include <cuda_runtime.h>
#include <cuda_fp16.h>
#include <cstdint>

// ---------------------------------------------------------------------------
// VSN on GB300 — Round 16: tail_fused = wlogits + enc_combine in one launch,
// warp-per-token, gv/bvn staged in smem. conv_mega + mega as R15.
// B=8,T=2048,NV=16,D=256 -> BT=16384, DIN=4096
// ---------------------------------------------------------------------------

#define BT_TOK 16384L
#define DDIM   256
#define DIN    4096

// ---------------- scratch (bytes) ----------------
#define O_VH    0ULL            // vars fp16 [16384,4096]          128MB
#define O_H1    134217728ULL    // h1 fp16 [16384,256]
#define O_E     159383552ULL    // E=glu+x fp16 16x[16384,256]     128MB
#define O_SKIP  293601280ULL    // skip fp32 [16384,16]
#define O_G1    294649856ULL    // Wg1^T fp16 [256,4096]
#define O_WF    296747008ULL    // Wfuse fp32 [256,32] + bfuse[32]
#define O_W1    296878080ULL    // Wv1^T fp16 16x[256,256]
#define O_W2    298975232ULL
#define O_W3    301072384ULL    // Wv3^T perm fp16 16x[512,256]
#define G_TOTAL 305266688ULL

__device__ __align__(1024) unsigned char g_buf[G_TOTAL];

// ---------------- helpers ----------------
__device__ __forceinline__ uint32_t smem_u32(const void* p) {
    uint32_t a;
    asm("{ .reg .u64 t; cvta.to.shared.u64 t, %1; cvt.u32.u64 %0, t; }" : "=r"(a) : "l"(p));
    return a;
}
__device__ __forceinline__ void cpasync16(uint32_t dst, const void* src) {
    asm volatile("cp.async.cg.shared.global [%0], [%1], 16;" :: "r"(dst), "l"(src));
}
#define CP_COMMIT() asm volatile("cp.async.commit_group;" ::: "memory")
#define CP_WAIT(n)  asm volatile("cp.async.wait_group %0;" :: "n"(n) : "memory")

__device__ __forceinline__ void ldsm_x4(uint32_t (&r)[4], uint32_t addr) {
    asm volatile("ldmatrix.sync.aligned.m8n8.x4.shared.b16 {%0,%1,%2,%3}, [%4];"
        : "=r"(r[0]), "=r"(r[1]), "=r"(r[2]), "=r"(r[3]) : "r"(addr));
}
__device__ __forceinline__ void mma16816(float (&c)[4], const uint32_t (&a)[4],
                                         uint32_t b0, uint32_t b1) {
    asm volatile("mma.sync.aligned.m16n8k16.row.col.f32.f16.f16.f32 "
        "{%0,%1,%2,%3}, {%4,%5,%6,%7}, {%8,%9}, {%0,%1,%2,%3};"
        : "+f"(c[0]), "+f"(c[1]), "+f"(c[2]), "+f"(c[3])
        : "r"(a[0]), "r"(a[1]), "r"(a[2]), "r"(a[3]), "r"(b0), "r"(b1));
}
__device__ __forceinline__ uint32_t hadd2_f32(uint32_t e, uint32_t x) {
    __half2 he = *reinterpret_cast<__half2*>(&e);
    __half2 hx = *reinterpret_cast<__half2*>(&x);
    float2 fe = __half22float2(he);
    float2 fx = __half22float2(hx);
    __half2 r = __floats2half2_rn(fe.x + fx.x, fe.y + fx.y);
    return *reinterpret_cast<uint32_t*>(&r);
}

// ---------------------------------------------------------------------------
// conv_mega: all conversions + Wfuse in one launch.
// ---------------------------------------------------------------------------
__device__ __noinline__ void dev_wT(const float* W, __half* TH, int K, int N,
                                    int bx, int by, int bz, float* smemf)
{
    float (*tile)[33] = reinterpret_cast<float (*)[33]>(smemf);
    const size_t vb = (size_t)bz * K * N;
    const int k0 = by * 32, n0 = bx * 32;
    const int tx = threadIdx.x & 31, ty = threadIdx.x >> 5;
#pragma unroll
    for (int i = 0; i < 4; i++)
        tile[ty + i * 8][tx] = W[vb + (size_t)(k0 + ty + i * 8) * N + n0 + tx];
    __syncthreads();
#pragma unroll
    for (int i = 0; i < 4; i++) {
        int n = ty + i * 8;
        TH[vb + (size_t)(n0 + n) * K + k0 + tx] = __float2half_rn(tile[tx][n]);
    }
}

__device__ __noinline__ void dev_wT3(const float* W, __half* TH,
                                     int bx, int by, int bz, float* smemf)
{
    float (*tile)[33] = reinterpret_cast<float (*)[33]>(smemf);
    const size_t vbs = (size_t)bz * 256 * 512;
    const size_t vbd = (size_t)bz * 512 * 256;
    const int k0 = by * 32, c0 = bx * 32;
    const int tx = threadIdx.x & 31, ty = threadIdx.x >> 5;
#pragma unroll
    for (int i = 0; i < 4; i++)
        tile[ty + i * 8][tx] = W[vbs + (size_t)(k0 + ty + i * 8) * 512 + c0 + tx];
    __syncthreads();
#pragma unroll
    for (int i = 0; i < 4; i++) {
        int c = c0 + ty + i * 8;
        int orow = (c < 256) ? (2 * c) : (2 * (c - 256) + 1);
        TH[vbd + (size_t)orow * 256 + k0 + tx] = __float2half_rn(tile[tx][ty + i * 8]);
    }
}

__device__ __noinline__ void dev_split(const float* x, __half* h, int bidx)
{
    size_t i = ((size_t)bidx * 512 + threadIdx.x * 2) * 4;
#pragma unroll
    for (int u = 0; u < 2; u++) {
        float4 v = *reinterpret_cast<const float4*>(x + i + u * 4);
        *reinterpret_cast<__half2*>(h + i + u * 4)     = __floats2half2_rn(v.x, v.y);
        *reinterpret_cast<__half2*>(h + i + u * 4 + 2) = __floats2half2_rn(v.z, v.w);
    }
}

__device__ __noinline__ void dev_wfuse(const float* Wg2, const float* Wg3,
                                       const float* bg2, const float* bg3,
                                       float* WF, int j, float* smemf)
{
    const int k = threadIdx.x;
    smemf[k] = Wg3[(size_t)k * 32 + j];
    __syncthreads();
    float s = 0.f;
    const float* wr = Wg2 + (size_t)k * 256;
#pragma unroll 8
    for (int m = 0; m < 256; m++) s += wr[m] * smemf[m];
    WF[k * 32 + j] = s;
    if (k == 0) {
        float b = bg3[j];
        for (int m = 0; m < 256; m++) b += bg2[m] * smemf[m];
        WF[256 * 32 + j] = b;
    }
}

__global__ __launch_bounds__(256)
void conv_mega(const float* __restrict__ vars, __half* __restrict__ VH,
               const float* __restrict__ Wg1, __half* __restrict__ G1T,
               const float* __restrict__ Wg2, const float* __restrict__ Wg3,
               const float* __restrict__ bg2, const float* __restrict__ bg3,
               float* __restrict__ WF,
               const float* __restrict__ Wv1, __half* __restrict__ W1T,
               const float* __restrict__ Wv2, __half* __restrict__ W2T,
               const float* __restrict__ Wv3, __half* __restrict__ W3T)
{
    __shared__ float smemf[32 * 33];
    const int b = blockIdx.x;
    if (b < 32) {
        dev_wfuse(Wg2, Wg3, bg2, bg3, WF, b, smemf);
    } else if (b < 1056) {
        int i = b - 32;   dev_wT(Wg1, G1T, 4096, 256, i & 7, i >> 3, 0, smemf);
    } else if (b < 2080) {
        int i = b - 1056; dev_wT(Wv1, W1T, 256, 256, i & 7, (i >> 3) & 7, i >> 6, smemf);
    } else if (b < 3104) {
        int i = b - 2080; dev_wT(Wv2, W2T, 256, 256, i & 7, (i >> 3) & 7, i >> 6, smemf);
    } else if (b < 5152) {
        int i = b - 3104; dev_wT3(Wv3, W3T, i & 15, (i >> 4) & 7, i >> 7, smemf);
    } else {
        dev_split(vars, VH, b - 5152);
    }
}

// ---------------------------------------------------------------------------
#define RS 72
#define OFF_B  18432
#define ST_SIZE 36864
#define SMEM_TOT 110592

#define ACH 9216u
#define FA0 0u
#define FA1 36864u
#define FWB 73728u

// ---- G1 GEMM body ----
__device__ __noinline__ void dev_g1(unsigned char* sm, uint32_t sb,
                                    const __half* VH, const __half* G1T,
                                    const float* bg1, __half* H1, int bidx)
{
    const int tid = threadIdx.x;
    const int lane = tid & 31, wid = tid >> 5;
    const int wm = wid & 1, wn = wid >> 1;
    const int nb = (bidx & 1) * 128;
    const int m0 = (bidx >> 1) * 128;

    const __half* Ap  = VH + (size_t)m0 * DIN;
    const __half* Bhp = G1T + (size_t)nb * DIN;
    const int lr = tid >> 3;
    const int lc = (tid & 7) * 8;

    float acc[4][4][4];
#pragma unroll
    for (int i = 0; i < 4; i++)
#pragma unroll
        for (int j = 0; j < 4; j++)
#pragma unroll
            for (int k = 0; k < 4; k++) acc[i][j][k] = 0.f;

    auto load_stage = [&](int s, int k0) {
        const uint32_t base = sb + s * ST_SIZE;
#pragma unroll
        for (int t = 0; t < 4; t++) {
            const int row = lr + t * 32;
            const uint32_t doff = (uint32_t)(row * RS + lc) * 2;
            cpasync16(base + doff,         Ap  + (size_t)row * DIN + k0 + lc);
            cpasync16(base + OFF_B + doff, Bhp + (size_t)row * DIN + k0 + lc);
        }
    };

    const uint32_t aoff = (uint32_t)(((wm * 64 + (lane & 15)) * RS + (lane >> 4) * 8) * 2);
    const uint32_t boff = (uint32_t)(((wn * 32 + (lane & 15)) * RS + (lane >> 4) * 8) * 2);

    load_stage(0, 0);  CP_COMMIT();
    load_stage(1, 64); CP_COMMIT();

    int sidx = 0;
    for (int c = 0; c < 64; c++) {
        CP_WAIT(1);
        __syncthreads();
        const uint32_t base = sb + sidx * ST_SIZE;
#pragma unroll
        for (int kc = 0; kc < 64; kc += 16) {
            uint32_t a[4][4], bh[2][4];
#pragma unroll
            for (int mt = 0; mt < 4; mt++)
                ldsm_x4(a[mt], base + aoff + mt * (16 * RS * 2) + kc * 2);
#pragma unroll
            for (int p = 0; p < 2; p++)
                ldsm_x4(bh[p], base + OFF_B + boff + p * (16 * RS * 2) + kc * 2);
#pragma unroll
            for (int mt = 0; mt < 4; mt++)
#pragma unroll
                for (int q = 0; q < 4; q++)
                    mma16816(acc[mt][q], a[mt], bh[q >> 1][q & 1], bh[q >> 1][(q & 1) + 2]);
        }
        __syncthreads();
        if (c + 2 < 64) {
            int ns = sidx + 2; if (ns >= 3) ns -= 3;
            load_stage(ns, (c + 2) * 64);
        }
        CP_COMMIT();
        if (++sidx == 3) sidx = 0;
    }

    const int gid = lane >> 2, tig = lane & 3;
#pragma unroll
    for (int mt = 0; mt < 4; mt++) {
#pragma unroll
        for (int q = 0; q < 4; q++) {
            const int m = m0 + wm * 64 + mt * 16 + gid;
            const int n = nb + wn * 32 + q * 8 + tig * 2;
            const float b0 = bg1[n], b1 = bg1[n + 1];
            float x0 = acc[mt][q][0] + b0, x1 = acc[mt][q][1] + b1;
            float y0 = acc[mt][q][2] + b0, y1 = acc[mt][q][3] + b1;
            x0 = (x0 > 0.f) ? x0 : expm1f(x0);
            x1 = (x1 > 0.f) ? x1 : expm1f(x1);
            y0 = (y0 > 0.f) ? y0 : expm1f(y0);
            y1 = (y1 > 0.f) ? y1 : expm1f(y1);
            __half* d0 = H1 + (size_t)m * 256 + n;
            *reinterpret_cast<__half2*>(d0) = __floats2half2_rn(x0, x1);
            *reinterpret_cast<__half2*>(d0 + 8 * 256) = __floats2half2_rn(y0, y1);
        }
    }
}

// ---- skip body ----
__device__ __noinline__ void dev_skip(unsigned char* sm,
                                      const __half* vh, const float* Wgs,
                                      const float* bgs, float* skipOut, int bidx)
{
    __half (*As)[256] = reinterpret_cast<__half (*)[256]>(sm);
    float (*Ws)[16]  = reinterpret_cast<float (*)[16]>(sm + 8192);
    const int tid = threadIdx.x;
    const long t0 = (long)bidx * 16;
    const int o = tid & 15;
    const int tr = tid >> 4;
    float s = 0.f;
    for (int k0 = 0; k0 < DIN; k0 += 256) {
        {
            const int r = tid >> 4;
            const int cc = (tid & 15) * 16;
            *reinterpret_cast<uint4*>(&As[r][cc]) =
                *reinterpret_cast<const uint4*>(vh + (t0 + r) * DIN + k0 + cc);
            *reinterpret_cast<uint4*>(&As[r][cc + 8]) =
                *reinterpret_cast<const uint4*>(vh + (t0 + r) * DIN + k0 + cc + 8);
        }
        {
            const int r = tid;
            *reinterpret_cast<float4*>(&Ws[r][0])  = *reinterpret_cast<const float4*>(Wgs + (long)(k0 + r) * 16 + 0);
            *reinterpret_cast<float4*>(&Ws[r][4])  = *reinterpret_cast<const float4*>(Wgs + (long)(k0 + r) * 16 + 4);
            *reinterpret_cast<float4*>(&Ws[r][8])  = *reinterpret_cast<const float4*>(Wgs + (long)(k0 + r) * 16 + 8);
            *reinterpret_cast<float4*>(&Ws[r][12]) = *reinterpret_cast<const float4*>(Wgs + (long)(k0 + r) * 16 + 12);
        }
        __syncthreads();
#pragma unroll 16
        for (int kk = 0; kk < 256; kk++) s += __half2float(As[tr][kk]) * Ws[kk][o];
        __syncthreads();
    }
    skipOut[(t0 + tr) * 16 + o] = s + bgs[o];
}

// ---- fused per-variable chain body ----
__device__ __noinline__ void dev_fused(unsigned char* sm, uint32_t sb,
                                       const __half* VH,
                                       const __half* W1T, const __half* W2T,
                                       const __half* W3T,
                                       const float* bv1, const float* bv2,
                                       const float* bv3, __half* E, int bidx)
{
    const int tid = threadIdx.x;
    const int lane = tid & 31, wid = tid >> 5;
    const int wm = wid & 1, wn = wid >> 1;
    const int gid = lane >> 2, tig = lane & 3;
    const int v = bidx >> 8;
    const int m0 = (bidx & 255) * 64;

    {
        const __half* xp = VH + (size_t)m0 * DIN + v * 256;
#pragma unroll
        for (int t = 0; t < 8; t++) {
            const int id = tid + t * 256;
            const int ch = id >> 9;
            const int rem = id & 511;
            const int row = rem >> 3;
            const int lc8 = (rem & 7) * 8;
            cpasync16(sb + FA0 + ch * ACH + (uint32_t)(row * RS + lc8) * 2,
                      xp + (size_t)row * DIN + ch * 64 + lc8);
        }
        CP_COMMIT();
    }

    const uint32_t aoff = (uint32_t)(((wm * 32 + (lane & 15)) * RS + (lane >> 4) * 8) * 2);
    const uint32_t boff = (uint32_t)(((wn * 32 + (lane & 15)) * RS + (lane >> 4) * 8) * 2);
    const int lr = tid >> 3;
    const int lc = (tid & 7) * 8;

    for (int stage = 0; stage < 3; stage++) {
        const __half* W = (stage == 0) ? (W1T + (size_t)v * 65536)
                        : (stage == 1) ? (W2T + (size_t)v * 65536)
                                       : (W3T + (size_t)v * 131072);
        const int nPass = (stage == 2) ? 4 : 2;
        const uint32_t aBuf = (stage == 1) ? FA1 : FA0;
        const uint32_t oBuf = (stage == 0) ? FA1 : FA0;

        for (int np = 0; np < nPass; np++) {
            float acc[2][4][4];
#pragma unroll
            for (int i = 0; i < 2; i++)
#pragma unroll
                for (int j = 0; j < 4; j++)
#pragma unroll
                    for (int k = 0; k < 4; k++) acc[i][j][k] = 0.f;

            const __half* Wp = W + (size_t)(np * 128) * 256;
#pragma unroll
            for (int pc = 0; pc < 2; pc++) {
#pragma unroll
                for (int t = 0; t < 4; t++) {
                    const int row = lr + t * 32;
                    cpasync16(sb + FWB + pc * 18432 + (uint32_t)(row * RS + lc) * 2,
                              Wp + (size_t)row * 256 + pc * 64 + lc);
                }
                CP_COMMIT();
            }

            for (int c = 0; c < 4; c++) {
                if (c < 3) { CP_WAIT(1); } else { CP_WAIT(0); }
                __syncthreads();
                const uint32_t abase = sb + aBuf + c * ACH;
                const uint32_t bbase = sb + FWB + (c & 1) * 18432;
#pragma unroll
                for (int kc = 0; kc < 64; kc += 16) {
                    uint32_t a[2][4], bh[2][4];
#pragma unroll
                    for (int mt = 0; mt < 2; mt++)
                        ldsm_x4(a[mt], abase + aoff + mt * (16 * RS * 2) + kc * 2);
#pragma unroll
                    for (int p = 0; p < 2; p++)
                        ldsm_x4(bh[p], bbase + boff + p * (16 * RS * 2) + kc * 2);
#pragma unroll
                    for (int mt = 0; mt < 2; mt++)
#pragma unroll
                        for (int q = 0; q < 4; q++)
                            mma16816(acc[mt][q], a[mt], bh[q >> 1][q & 1], bh[q >> 1][(q & 1) + 2]);
                }
                __syncthreads();
                if (c + 2 < 4) {
#pragma unroll
                    for (int t = 0; t < 4; t++) {
                        const int row = lr + t * 32;
                        cpasync16(sb + FWB + (c & 1) * 18432 + (uint32_t)(row * RS + lc) * 2,
                                  Wp + (size_t)row * 256 + (c + 2) * 64 + lc);
                    }
                    CP_COMMIT();
                }
            }

            if (stage < 2) {
                const float* bp = ((stage == 0) ? bv1 : bv2) + (size_t)v * 256;
                __half* ob = reinterpret_cast<__half*>(sm) + (oBuf >> 1);
#pragma unroll
                for (int mt = 0; mt < 2; mt++) {
#pragma unroll
                    for (int q = 0; q < 4; q++) {
                        const int m = wm * 32 + mt * 16 + gid;
                        const int gn = np * 128 + wn * 32 + q * 8 + tig * 2;
                        const float b0 = bp[gn], b1 = bp[gn + 1];
                        float x0 = acc[mt][q][0] + b0, x1 = acc[mt][q][1] + b1;
                        float y0 = acc[mt][q][2] + b0, y1 = acc[mt][q][3] + b1;
                        if (stage == 0) {
                            x0 = (x0 > 0.f) ? x0 : expm1f(x0);
                            x1 = (x1 > 0.f) ? x1 : expm1f(x1);
                            y0 = (y0 > 0.f) ? y0 : expm1f(y0);
                            y1 = (y1 > 0.f) ? y1 : expm1f(y1);
                        }
                        const int ch = gn >> 6;
                        const int ko = gn & 63;
                        __half* d0 = ob + ch * (ACH / 2) + m * RS + ko;
                        *reinterpret_cast<__half2*>(d0) = __floats2half2_rn(x0, x1);
                        *reinterpret_cast<__half2*>(d0 + 8 * RS) = __floats2half2_rn(y0, y1);
                    }
                }
                __syncthreads();
            } else {
                const float* bp = bv3 + (size_t)v * 512;
                const int jbase = np * 64;
                __half* Eg = reinterpret_cast<__half*>(sm) + (FA1 >> 1);
#pragma unroll
                for (int mt = 0; mt < 2; mt++) {
#pragma unroll
                    for (int q = 0; q < 4; q++) {
                        const int nl = wn * 32 + q * 8 + tig * 2;
                        const int jl = nl >> 1;
                        const int jg = jbase + jl;
                        const float ba = bp[jg], bb = bp[jg + 256];
                        const int r0 = wm * 32 + mt * 16 + gid;
                        float a0 = acc[mt][q][0] + ba, b0 = acc[mt][q][1] + bb;
                        float a1 = acc[mt][q][2] + ba, b1 = acc[mt][q][3] + bb;
                        Eg[r0 * 64 + jl]       = __float2half_rn(a0 * (1.f / (1.f + expf(-b0))));
                        Eg[(r0 + 8) * 64 + jl] = __float2half_rn(a1 * (1.f / (1.f + expf(-b1))));
                    }
                }
                __syncthreads();
                const int row = tid >> 2;
                const int chh = (tid & 3) * 16;
                const __half* src = Eg + row * 64 + chh;
                const __half* xsrc = VH + (size_t)(m0 + row) * DIN + v * 256 + jbase + chh;
                __half* dst = E + ((size_t)v * BT_TOK + m0 + row) * 256 + jbase + chh;
#pragma unroll
                for (int u = 0; u < 2; u++) {
                    uint4 ev = *reinterpret_cast<const uint4*>(src + u * 8);
                    uint4 xv = *reinterpret_cast<const uint4*>(xsrc + u * 8);
                    uint4 ov;
                    ov.x = hadd2_f32(ev.x, xv.x);
                    ov.y = hadd2_f32(ev.y, xv.y);
                    ov.z = hadd2_f32(ev.z, xv.z);
                    ov.w = hadd2_f32(ev.w, xv.w);
                    *reinterpret_cast<uint4*>(dst + u * 8) = ov;
                }
                __syncthreads();
            }
        }
    }
}

// ---- mega kernel ----
__global__ __launch_bounds__(256, 2)
void mega_kernel(const __half* __restrict__ VH,
                 const __half* __restrict__ G1T, const float* __restrict__ bg1,
                 __half* __restrict__ H1,
                 const float* __restrict__ Wgs, const float* __restrict__ bgs,
                 float* __restrict__ SKP,
                 const __half* __restrict__ W1T, const __half* __restrict__ W2T,
                 const __half* __restrict__ W3T,
                 const float* __restrict__ bv1, const float* __restrict__ bv2,
                 const float* __restrict__ bv3, __half* __restrict__ E)
{
    extern __shared__ __align__(1024) unsigned char sm[];
    const uint32_t sb = smem_u32(sm);
    const int b = blockIdx.x;
    if (b < 256) {
        dev_g1(sm, sb, VH, G1T, bg1, H1, b);
    } else if (b < 1280) {
        dev_skip(sm, VH, Wgs, bgs, SKP, b - 256);
    } else {
        dev_fused(sm, sb, VH, W1T, W2T, W3T, bv1, bv2, bv3, E, b - 1280);
    }
}

// ---------------------------------------------------------------------------
// tail_fused: 2048 blocks x 8 tokens. Phase1 wlogits (warp/token, Wfuse smem);
// Phase2 enc (warp/token over all 16 vars; gv/bvn staged in smem).
// ---------------------------------------------------------------------------
__global__ __launch_bounds__(256, 2)
void tail_fused(const __half* __restrict__ h1, const float* __restrict__ WF,
                const float* __restrict__ gg, const float* __restrict__ bgn,
                const float* __restrict__ skipIn, const __half* __restrict__ E,
                const float* __restrict__ gv, const float* __restrict__ bvn,
                float* __restrict__ outp, float* __restrict__ wout)
{
    __shared__ float buf[8192];     // phase1: Wfuse; phase2: gv(4096)+bvn(4096)
    __shared__ float bf[32];
    __shared__ float sws[8][16];
    const int tid = threadIdx.x;
    const int lane = tid & 31, wid = tid >> 5;
    const long t = (long)blockIdx.x * 8 + wid;

    // ---- phase 1: wlogits ----
#pragma unroll
    for (int i = 0; i < 32; i++) buf[tid + i * 256] = WF[tid + i * 256];
    if (tid < 32) bf[tid] = WF[256 * 32 + tid];
    __syncthreads();

    {
        const __half* h1t = h1 + t * 256;
        float s = bf[lane];
#pragma unroll 4
        for (int k = 0; k < 256; k += 8) {
            uint4 raw = *reinterpret_cast<const uint4*>(h1t + k);
            const __half2* hh = reinterpret_cast<const __half2*>(&raw);
#pragma unroll
            for (int i = 0; i < 4; i++) {
                float2 f = __half22float2(hh[i]);
                s += f.x * buf[(k + 2 * i + 0) * 32 + lane];
                s += f.y * buf[(k + 2 * i + 1) * 32 + lane];
            }
        }
        float bhalf = __shfl_down_sync(0xffffffffu, s, 16);
        float r = 0.f;
        if (lane < 16)
            r = s * (1.f / (1.f + expf(-bhalf))) + skipIn[t * 16 + lane];
        float sum = r;
        for (int m = 8; m; m >>= 1) sum += __shfl_xor_sync(0xffffffffu, sum, m, 16);
        float mean = sum * (1.f / 16.f);
        float d = r - mean;
        float vs = d * d;
        for (int m = 8; m; m >>= 1) vs += __shfl_xor_sync(0xffffffffu, vs, m, 16);
        float rstd = rsqrtf(vs * (1.f / 16.f) + 1e-6f);
        float ln = 0.f;
        if (lane < 16) ln = d * rstd * gg[lane] + bgn[lane];
        float mx = ln;
        for (int m = 8; m; m >>= 1) mx = fmaxf(mx, __shfl_xor_sync(0xffffffffu, mx, m, 16));
        float e = (lane < 16) ? expf(ln - mx) : 0.f;
        float se = e;
        for (int m = 8; m; m >>= 1) se += __shfl_xor_sync(0xffffffffu, se, m, 16);
        if (lane < 16) {
            float wv = e / se;
            wout[t * 16 + lane] = wv;
            sws[wid][lane] = wv;
        }
    }
    __syncthreads();

    // ---- stage gv/bvn into buf ----
#pragma unroll
    for (int i = 0; i < 4; i++) {
        *reinterpret_cast<float4*>(&buf[tid * 4 + i * 1024]) =
            *reinterpret_cast<const float4*>(gv + tid * 4 + i * 1024);
        *reinterpret_cast<float4*>(&buf[4096 + tid * 4 + i * 1024]) =
            *reinterpret_cast<const float4*>(bvn + tid * 4 + i * 1024);
    }
    __syncthreads();

    // ---- phase 2: enc combine, warp per token, all 16 vars ----
    const int c0 = lane * 8;
    float acc8[8];
#pragma unroll
    for (int i = 0; i < 8; i++) acc8[i] = 0.f;
#pragma unroll 4
    for (int v = 0; v < 16; v++) {
        uint4 rawE = *reinterpret_cast<const uint4*>(
            E + ((size_t)v * BT_TOK + t) * 256 + c0);
        const __half2* he = reinterpret_cast<const __half2*>(&rawE);
        float e[8];
#pragma unroll
        for (int i = 0; i < 4; i++) {
            float2 fe = __half22float2(he[i]);
            e[2 * i]     = fe.x;
            e[2 * i + 1] = fe.y;
        }
        float s1 = 0.f, s2 = 0.f;
#pragma unroll
        for (int i = 0; i < 8; i++) { s1 += e[i]; s2 += e[i] * e[i]; }
#pragma unroll
        for (int m = 16; m; m >>= 1) {
            s1 += __shfl_xor_sync(0xffffffffu, s1, m);
            s2 += __shfl_xor_sync(0xffffffffu, s2, m);
        }
        const float mean = s1 * (1.f / 256.f);
        const float var = s2 * (1.f / 256.f) - mean * mean;
        const float rstd = rsqrtf(var + 1e-6f);
        const float w = sws[wid][v];
        const float4 g0 = *reinterpret_cast<const float4*>(&buf[v * 256 + c0]);
        const float4 g1 = *reinterpret_cast<const float4*>(&buf[v * 256 + c0 + 4]);
        const float4 b0 = *reinterpret_cast<const float4*>(&buf[4096 + v * 256 + c0]);
        const float4 b1 = *reinterpret_cast<const float4*>(&buf[4096 + v * 256 + c0 + 4]);
        const float gva[8] = {g0.x, g0.y, g0.z, g0.w, g1.x, g1.y, g1.z, g1.w};
        const float bva[8] = {b0.x, b0.y, b0.z, b0.w, b1.x, b1.y, b1.z, b1.w};
#pragma unroll
        for (int i = 0; i < 8; i++)
            acc8[i] += ((e[i] - mean) * rstd * gva[i] + bva[i]) * w;
    }
    float4 o0, o1;
    o0.x = acc8[0]; o0.y = acc8[1]; o0.z = acc8[2]; o0.w = acc8[3];
    o1.x = acc8[4]; o1.y = acc8[5]; o1.z = acc8[6]; o1.w = acc8[7];
    float* dp = outp + t * DDIM + c0;
    *reinterpret_cast<float4*>(dp) = o0;
    *reinterpret_cast<float4*>(dp + 4) = o1;
}

// ---------------------------------------------------------------------------
extern "C" void kernel_launch(void* const* d_in, const int* in_sizes, int n_in,
                              void* d_out, int out_size)
{
    const float* vars = (const float*)d_in[0];
    const float* Wg1  = (const float*)d_in[1];
    const float* bg1  = (const float*)d_in[2];
    const float* Wg2  = (const float*)d_in[3];
    const float* bg2  = (const float*)d_in[4];
    const float* Wg3  = (const float*)d_in[5];
    const float* bg3  = (const float*)d_in[6];
    const float* Wgs  = (const float*)d_in[7];
    const float* bgs  = (const float*)d_in[8];
    const float* gg   = (const float*)d_in[9];
    const float* bgn  = (const float*)d_in[10];
    const float* Wv1  = (const float*)d_in[11];
    const float* bv1  = (const float*)d_in[12];
    const float* Wv2  = (const float*)d_in[13];
    const float* bv2  = (const float*)d_in[14];
    const float* Wv3  = (const float*)d_in[15];
    const float* bv3  = (const float*)d_in[16];
    const float* gv   = (const float*)d_in[17];
    const float* bvn  = (const float*)d_in[18];

    float* out  = (float*)d_out;
    float* wout = out + BT_TOK * DDIM;

    unsigned char* gb = nullptr;
    cudaGetSymbolAddress((void**)&gb, g_buf);
    __half* VH  = (__half*)(gb + O_VH);
    __half* H1  = (__half*)(gb + O_H1);
    __half* E   = (__half*)(gb + O_E);
    float*  SKP = (float*)(gb + O_SKIP);
    __half* G1T = (__half*)(gb + O_G1);
    float*  WF  = (float*)(gb + O_WF);
    __half* W1T = (__half*)(gb + O_W1);
    __half* W2T = (__half*)(gb + O_W2);
    __half* W3T = (__half*)(gb + O_W3);

    cudaFuncSetAttribute(mega_kernel, cudaFuncAttributeMaxDynamicSharedMemorySize, SMEM_TOT);

    // all conversions + Wfuse in one launch
    conv_mega<<<37920, 256>>>(vars, VH, Wg1, G1T, Wg2, Wg3, bg2, bg3, WF,
                              Wv1, W1T, Wv2, W2T, Wv3, W3T);

    // mega: G1 + skip + fused per-variable chain, co-scheduled
    mega_kernel<<<5376, 256, SMEM_TOT>>>(VH, G1T, bg1, H1, Wgs, bgs, SKP,
                                         W1T, W2T, W3T, bv1, bv2, bv3, E);

    // tail: wlogits + enc combine fused
    tail_fused<<<2048, 256>>>(H1, WF, gg, bgn, SKP, E, gv, bvn, out, wout);
}